// round 1
// baseline (speedup 1.0000x reference)
#include <cuda_runtime.h>
#include <math.h>

#define EMB   30
#define KTOP  5
#define QMAX  2048
#define DMAX  8192
#define WPB   16      // warps (=queries) per block in main kernel
#define CHUNK 64      // docs staged per shared-memory tile
#define PAD   33      // row stride in shared (coprime with 32 -> conflict-free)

// ---------------- device scratch (static: no runtime allocation) ----------------
__device__ float g_qconv [QMAX*EMB];
__device__ float g_d1conv[DMAX*EMB];
__device__ float g_d2conv[DMAX*EMB];
__device__ float g_invq  [QMAX];
__device__ float g_invqc [QMAX];
__device__ float g_invd1 [DMAX];
__device__ float g_invd1c[DMAX];
__device__ float g_invd2 [DMAX];
__device__ float g_invd2c[DMAX];
__device__ float g_logits[QMAX];
__device__ float g_qw    [QMAX];
__device__ float g_lo1   [QMAX];
__device__ float g_lo2   [QMAX];

__device__ __forceinline__ float leaky(float x) { return x > 0.f ? x : 0.1f * x; }

// ---------------- kernel 1: conv + residual + norms + qw logits ----------------
// one warp per row; lane o (<30) computes output channel o.
__global__ void conv_kernel(const float* __restrict__ qe,
                            const float* __restrict__ d1,
                            const float* __restrict__ d2,
                            const float* __restrict__ qidf,
                            const float* __restrict__ Wc,   // [30,30,3] row-major
                            const float* __restrict__ bc,   // [30]
                            const float* __restrict__ Wqw,  // [31]
                            int Q, int D)
{
    int warpsPerBlock = blockDim.x >> 5;
    int gw   = blockIdx.x * warpsPerBlock + (threadIdx.x >> 5);
    int lane = threadIdx.x & 31;
    int total = Q + 2 * D;
    if (gw >= total) return;

    const float* x; float* y; int L, l, which;
    if (gw < Q)          { x = qe; y = g_qconv;  L = Q; l = gw;         which = 0; }
    else if (gw < Q + D) { x = d1; y = g_d1conv; L = D; l = gw - Q;     which = 1; }
    else                 { x = d2; y = g_d2conv; L = D; l = gw - Q - D; which = 2; }

    int o = lane;
    float yv = 0.f, xval = 0.f;
    if (o < EMB) {
        float acc = __ldg(&bc[o]);
        #pragma unroll
        for (int t = 0; t < 3; t++) {
            int ll = l + t - 1;
            if (ll >= 0 && ll < L) {
                const float* xr = x + (size_t)ll * EMB;
                #pragma unroll
                for (int i = 0; i < EMB; i++)
                    acc += __ldg(&xr[i]) * __ldg(&Wc[o * 90 + i * 3 + t]);
            }
        }
        xval = __ldg(&x[(size_t)l * EMB + o]);
        yv = leaky(acc) + xval;
        y[(size_t)l * EMB + o] = yv;
    }

    float s_conv = (o < EMB) ? yv * yv     : 0.f;
    float s_orig = (o < EMB) ? xval * xval : 0.f;
    float lg     = (which == 0 && o < EMB) ? yv * __ldg(&Wqw[o]) : 0.f;
    #pragma unroll
    for (int off = 16; off; off >>= 1) {
        s_conv += __shfl_xor_sync(0xffffffffu, s_conv, off);
        s_orig += __shfl_xor_sync(0xffffffffu, s_orig, off);
        lg     += __shfl_xor_sync(0xffffffffu, lg,     off);
    }
    if (lane == 0) {
        float ic = 1.f / sqrtf(s_conv);
        float io = 1.f / sqrtf(s_orig);
        if (which == 0) {
            g_invqc[l] = ic; g_invq[l] = io;
            g_logits[l] = lg + __ldg(&qidf[l]) * __ldg(&Wqw[EMB]);
        } else if (which == 1) { g_invd1c[l] = ic; g_invd1[l] = io; }
        else                   { g_invd2c[l] = ic; g_invd2[l] = io; }
    }
}

// ---------------- kernel 2: softmax over Q logits (single block) ----------------
__global__ void softmax_kernel(int Q)
{
    __shared__ float red[1024];
    int tid = threadIdx.x;
    float m = -1e30f;
    for (int i = tid; i < Q; i += blockDim.x) m = fmaxf(m, g_logits[i]);
    red[tid] = m; __syncthreads();
    for (int s = blockDim.x >> 1; s; s >>= 1) {
        if (tid < s) red[tid] = fmaxf(red[tid], red[tid + s]);
        __syncthreads();
    }
    float mx = red[0];
    __syncthreads();
    float sum = 0.f;
    for (int i = tid; i < Q; i += blockDim.x) sum += expf(g_logits[i] - mx);
    red[tid] = sum; __syncthreads();
    for (int s = blockDim.x >> 1; s; s >>= 1) {
        if (tid < s) red[tid] += red[tid + s];
        __syncthreads();
    }
    float inv = 1.f / red[0];
    for (int i = tid; i < Q; i += blockDim.x)
        g_qw[i] = expf(g_logits[i] - mx) * inv;
}

// ---------------- top-5 helpers ----------------
#define TOPK_INSERT(t, v) do {                                        \
    float _v = (v);                                                   \
    if (_v > t[4]) {                                                  \
        t[4] = _v; float _tmp;                                        \
        if (t[4] > t[3]) { _tmp = t[3]; t[3] = t[4]; t[4] = _tmp; }   \
        if (t[3] > t[2]) { _tmp = t[2]; t[2] = t[3]; t[3] = _tmp; }   \
        if (t[2] > t[1]) { _tmp = t[1]; t[1] = t[2]; t[2] = _tmp; }   \
        if (t[1] > t[0]) { _tmp = t[0]; t[0] = t[1]; t[1] = _tmp; }   \
    } } while (0)

__device__ __forceinline__ void warp_merge_top5(float t[KTOP])
{
    #pragma unroll
    for (int off = 16; off; off >>= 1) {
        float b0 = __shfl_xor_sync(0xffffffffu, t[0], off);
        float b1 = __shfl_xor_sync(0xffffffffu, t[1], off);
        float b2 = __shfl_xor_sync(0xffffffffu, t[2], off);
        float b3 = __shfl_xor_sync(0xffffffffu, t[3], off);
        float b4 = __shfl_xor_sync(0xffffffffu, t[4], off);
        float a0 = t[0], a1 = t[1], a2 = t[2], a3 = t[3], a4 = t[4];
        #pragma unroll
        for (int k = 0; k < KTOP; k++) {
            bool ta = a0 >= b0;
            t[k] = ta ? a0 : b0;
            if (ta) { a0 = a1; a1 = a2; a2 = a3; a3 = a4; a4 = -1e30f; }
            else    { b0 = b1; b1 = b2; b2 = b3; b3 = b4; b4 = -1e30f; }
        }
    }
}

__device__ __forceinline__ float mlp_out(const float temp[6],
                                         const float* __restrict__ Wq1,
                                         const float* __restrict__ Wq2)
{
    float out = 0.f;
    #pragma unroll
    for (int h = 0; h < 8; h++) {
        float hh = 0.f;
        #pragma unroll
        for (int j = 0; j < 6; j++) hh += __ldg(&Wq1[h * 6 + j]) * temp[j];
        out += __ldg(&Wq2[h]) * leaky(hh);
    }
    return out;
}

// ---------------- kernel 3: fused sims + top-k + per-query MLP ----------------
__global__ void main_kernel(const float* __restrict__ qe,
                            const float* __restrict__ d1e,
                            const float* __restrict__ d2e,
                            const float* __restrict__ Wq1,
                            const float* __restrict__ Wq2,
                            int Q, int D)
{
    __shared__ float sd[4][CHUNK * PAD];
    __shared__ float snorm[4][CHUNK];

    int warp = threadIdx.x >> 5, lane = threadIdx.x & 31;
    int q = blockIdx.x * WPB + warp;
    bool active = (q < Q);

    float qv[EMB], qc[EMB];
    float invq = 0.f, invqc = 0.f;
    if (active) {
        #pragma unroll
        for (int e = 0; e < EMB; e++) {
            qv[e] = __ldg(&qe[(size_t)q * EMB + e]);
            qc[e] = g_qconv[(size_t)q * EMB + e];
        }
        invq = g_invq[q]; invqc = g_invqc[q];
    } else {
        #pragma unroll
        for (int e = 0; e < EMB; e++) { qv[e] = 0.f; qc[e] = 0.f; }
    }

    float ti1[KTOP], ti2[KTOP], ts1[KTOP], ts2[KTOP];
    #pragma unroll
    for (int k = 0; k < KTOP; k++) { ti1[k] = ti2[k] = ts1[k] = ts2[k] = -1e30f; }
    int c1 = 0, c2 = 0;

    for (int base = 0; base < D; base += CHUNK) {
        int nvalid = min(CHUNK, D - base);
        __syncthreads();
        // cooperative, coalesced staging of 4 doc tiles
        for (int idx = threadIdx.x; idx < 4 * CHUNK * EMB; idx += blockDim.x) {
            int a = idx / (CHUNK * EMB);
            int rem = idx - a * (CHUNK * EMB);
            int r = rem / EMB, e = rem - r * EMB;
            float v = 0.f;
            if (r < nvalid) {
                const float* src = (a == 0) ? d1e : (a == 1) ? d2e
                                  : (a == 2) ? g_d1conv : g_d2conv;
                v = __ldg(&src[(size_t)(base + r) * EMB + e]);
            }
            sd[a][r * PAD + e] = v;
        }
        for (int idx = threadIdx.x; idx < 4 * CHUNK; idx += blockDim.x) {
            int a = idx / CHUNK, r = idx - a * CHUNK;
            float v = 0.f;
            if (r < nvalid) {
                const float* src = (a == 0) ? g_invd1 : (a == 1) ? g_invd2
                                  : (a == 2) ? g_invd1c : g_invd2c;
                v = src[base + r];
            }
            snorm[a][r] = v;
        }
        __syncthreads();

        if (active) {
            #pragma unroll
            for (int half = 0; half < 2; half++) {
                int d = lane + half * 32;
                if (d >= nvalid) continue;
                const float* r1 = &sd[0][d * PAD];
                const float* r2 = &sd[1][d * PAD];
                const float* r3 = &sd[2][d * PAD];
                const float* r4 = &sd[3][d * PAD];
                float a1 = 0.f, a2 = 0.f, a3 = 0.f, a4 = 0.f;
                #pragma unroll
                for (int e = 0; e < EMB; e++) {
                    a1 += qv[e] * r1[e];
                    a2 += qv[e] * r2[e];
                    a3 += qc[e] * r3[e];
                    a4 += qc[e] * r4[e];
                }
                float s1 = a1 * invq  * snorm[0][d];
                float s2 = a2 * invq  * snorm[1][d];
                float s3 = a3 * invqc * snorm[2][d];
                float s4 = a4 * invqc * snorm[3][d];
                if (s1 > 0.999f) c1++;
                if (s2 > 0.999f) c2++;
                TOPK_INSERT(ti1, s1);
                TOPK_INSERT(ti2, s2);
                TOPK_INSERT(ts1, s3);
                TOPK_INSERT(ts2, s4);
            }
        }
    }

    // warp reductions
    warp_merge_top5(ti1);
    warp_merge_top5(ti2);
    warp_merge_top5(ts1);
    warp_merge_top5(ts2);
    #pragma unroll
    for (int off = 16; off; off >>= 1) {
        c1 += __shfl_xor_sync(0xffffffffu, c1, off);
        c2 += __shfl_xor_sync(0xffffffffu, c2, off);
    }

    if (active && lane == 0) {
        float w = g_qw[q];
        // doc1
        {
            float temp[6];
            temp[0] = (c1 > 0) ? 1.f : 0.f;
            temp[1] = fminf((float)c1, 5.f) * 0.2f;
            temp[2] = ti1[0];
            temp[3] = (ti1[0] + ti1[1] + ti1[2] + ti1[3] + ti1[4]) * 0.2f;
            temp[4] = ts1[0];
            temp[5] = (ts1[0] + ts1[1] + ts1[2] + ts1[3] + ts1[4]) * 0.2f;
            g_lo1[q] = mlp_out(temp, Wq1, Wq2) * w;
        }
        // doc2
        {
            float temp[6];
            temp[0] = (c2 > 0) ? 1.f : 0.f;
            temp[1] = fminf((float)c2, 5.f) * 0.2f;
            temp[2] = ti2[0];
            temp[3] = (ti2[0] + ti2[1] + ti2[2] + ti2[3] + ti2[4]) * 0.2f;
            temp[4] = ts2[0];
            temp[5] = (ts2[0] + ts2[1] + ts2[2] + ts2[3] + ts2[4]) * 0.2f;
            g_lo2[q] = mlp_out(temp, Wq1, Wq2) * w;
        }
    }
}

// ---------------- kernel 4: final reduction + scalars ----------------
__global__ void final_kernel(const float* __restrict__ gaf,
                             const float* __restrict__ baf,
                             const float* __restrict__ Wout,
                             float* __restrict__ out, int Q)
{
    __shared__ float r1[1024], r2[1024];
    int tid = threadIdx.x;
    float s1 = 0.f, s2 = 0.f;
    for (int i = tid; i < Q; i += blockDim.x) { s1 += g_lo1[i]; s2 += g_lo2[i]; }
    r1[tid] = s1; r2[tid] = s2; __syncthreads();
    for (int s = blockDim.x >> 1; s; s >>= 1) {
        if (tid < s) { r1[tid] += r1[tid + s]; r2[tid] += r2[tid + s]; }
        __syncthreads();
    }
    if (tid == 0) {
        float e1 = r1[0] / (float)Q;
        float e2 = r2[0] / (float)Q;
        float good = gaf[0] * Wout[0] + gaf[1] * Wout[1] + gaf[2] * Wout[2]
                   + gaf[3] * Wout[3] + e1 * Wout[4];
        float bad  = baf[0] * Wout[0] + baf[1] * Wout[1] + baf[2] * Wout[2]
                   + baf[3] * Wout[3] + e2 * Wout[4];
        float l = 1.f + bad - good;
        out[0] = (l > 0.f) ? l : 0.f;
        out[1] = good;
        out[2] = bad;
    }
}

// ---------------- launch ----------------
extern "C" void kernel_launch(void* const* d_in, const int* in_sizes, int n_in,
                              void* d_out, int out_size)
{
    const float* d1   = (const float*)d_in[0];
    const float* d2   = (const float*)d_in[1];
    const float* qe   = (const float*)d_in[2];
    const float* qidf = (const float*)d_in[3];
    const float* gaf  = (const float*)d_in[4];
    const float* baf  = (const float*)d_in[5];
    const float* Wc   = (const float*)d_in[6];
    const float* bc   = (const float*)d_in[7];
    const float* Wqw  = (const float*)d_in[8];
    const float* Wq1  = (const float*)d_in[9];
    const float* Wq2  = (const float*)d_in[10];
    const float* Wout = (const float*)d_in[11];

    int D = in_sizes[0] / EMB;
    int Q = in_sizes[2] / EMB;
    if (D > DMAX) D = DMAX;
    if (Q > QMAX) Q = QMAX;

    int totalRows = Q + 2 * D;
    int convWpb = 8;
    conv_kernel<<<(totalRows + convWpb - 1) / convWpb, convWpb * 32>>>(
        qe, d1, d2, qidf, Wc, bc, Wqw, Q, D);

    softmax_kernel<<<1, 1024>>>(Q);

    main_kernel<<<(Q + WPB - 1) / WPB, WPB * 32>>>(qe, d1, d2, Wq1, Wq2, Q, D);

    final_kernel<<<1, 1024>>>(gaf, baf, Wout, (float*)d_out, Q);
}

// round 3
// speedup vs baseline: 2.0712x; 2.0712x over previous
#include <cuda_runtime.h>
#include <math.h>

#define EMB     30
#define KTOP    5
#define QMAX    2048
#define DMAX    8192
#define QT      16      // queries per sim block
#define DT      256     // docs per shared tile
#define THREADS 256
#define DSTRIDE 36      // doc tile row stride (floats)
#define QSTRIDE 32      // padded row stride of global operand matrices (floats)

// ---------------- device scratch (static; zero-initialized) ----------------
__device__ float g_qN  [QMAX * QSTRIDE];
__device__ float g_qcN [QMAX * QSTRIDE];
__device__ float g_d1N [DMAX * QSTRIDE];
__device__ float g_d2N [DMAX * QSTRIDE];
__device__ float g_d1cN[DMAX * QSTRIDE];
__device__ float g_d2cN[DMAX * QSTRIDE];
__device__ float g_logits[QMAX];
__device__ float g_qw    [QMAX];
__device__ float2 g_pool [4 * QMAX];
__device__ int    g_cnt4 [4 * QMAX];

__device__ __forceinline__ float leaky(float x) { return x > 0.f ? x : 0.1f * x; }

// ---------------- kernel 1: conv + residual + norms -> normalized padded ----------------
__global__ void __launch_bounds__(256)
conv_kernel(const float* __restrict__ qe,
            const float* __restrict__ d1,
            const float* __restrict__ d2,
            const float* __restrict__ qidf,
            const float* __restrict__ Wc,   // [30,30,3]
            const float* __restrict__ bc,   // [30]
            const float* __restrict__ Wqw,  // [31]
            int Q, int D)
{
    int warpsPerBlock = blockDim.x >> 5;
    int gw   = blockIdx.x * warpsPerBlock + (threadIdx.x >> 5);
    int lane = threadIdx.x & 31;
    int total = Q + 2 * D;
    if (gw >= total) return;

    const float* x; float* yN; float* xN; int L, l, which;
    if (gw < Q)          { x = qe; yN = g_qcN;  xN = g_qN;  L = Q; l = gw;         which = 0; }
    else if (gw < Q + D) { x = d1; yN = g_d1cN; xN = g_d1N; L = D; l = gw - Q;     which = 1; }
    else                 { x = d2; yN = g_d2cN; xN = g_d2N; L = D; l = gw - Q - D; which = 2; }

    int o = lane;
    float yv = 0.f, xval = 0.f;
    if (o < EMB) {
        float acc = __ldg(&bc[o]);
        #pragma unroll
        for (int t = 0; t < 3; t++) {
            int ll = l + t - 1;
            if (ll >= 0 && ll < L) {
                const float* xr = x + (size_t)ll * EMB;
                #pragma unroll
                for (int i = 0; i < EMB; i++)
                    acc += __ldg(&xr[i]) * __ldg(&Wc[o * 90 + i * 3 + t]);
            }
        }
        xval = __ldg(&x[(size_t)l * EMB + o]);
        yv = leaky(acc) + xval;
    }

    float s_conv = yv * yv;
    float s_orig = xval * xval;
    float lg = (which == 0 && o < EMB) ? yv * __ldg(&Wqw[o]) : 0.f;
    #pragma unroll
    for (int off = 16; off; off >>= 1) {
        s_conv += __shfl_xor_sync(0xffffffffu, s_conv, off);
        s_orig += __shfl_xor_sync(0xffffffffu, s_orig, off);
        lg     += __shfl_xor_sync(0xffffffffu, lg,     off);
    }
    float ic = rsqrtf(s_conv);
    float io = rsqrtf(s_orig);
    yN[(size_t)l * QSTRIDE + o] = yv * ic;
    xN[(size_t)l * QSTRIDE + o] = xval * io;
    if (which == 0 && lane == 0)
        g_logits[l] = lg + __ldg(&qidf[l]) * __ldg(&Wqw[EMB]);
}

// ---------------- kernel 2: softmax over Q logits (single block, 256 thr) ----------------
__global__ void __launch_bounds__(256)
softmax_kernel(int Q)
{
    __shared__ float red[256];
    int tid = threadIdx.x;
    float m = -1e30f;
    for (int i = tid; i < Q; i += 256) m = fmaxf(m, g_logits[i]);
    red[tid] = m; __syncthreads();
    for (int s = 128; s; s >>= 1) {
        if (tid < s) red[tid] = fmaxf(red[tid], red[tid + s]);
        __syncthreads();
    }
    float mx = red[0];
    __syncthreads();
    float sum = 0.f;
    for (int i = tid; i < Q; i += 256) sum += expf(g_logits[i] - mx);
    red[tid] = sum; __syncthreads();
    for (int s = 128; s; s >>= 1) {
        if (tid < s) red[tid] += red[tid + s];
        __syncthreads();
    }
    float inv = 1.f / red[0];
    for (int i = tid; i < Q; i += 256)
        g_qw[i] = expf(g_logits[i] - mx) * inv;
}

// ---------------- top-5 helpers ----------------
#define TOPK_INSERT(t, v) do {                                        \
    float _v = (v);                                                   \
    if (_v > t[4]) {                                                  \
        t[4] = _v; float _tmp;                                        \
        if (t[4] > t[3]) { _tmp = t[3]; t[3] = t[4]; t[4] = _tmp; }   \
        if (t[3] > t[2]) { _tmp = t[2]; t[2] = t[3]; t[3] = _tmp; }   \
        if (t[2] > t[1]) { _tmp = t[1]; t[1] = t[2]; t[2] = _tmp; }   \
        if (t[1] > t[0]) { _tmp = t[0]; t[0] = t[1]; t[1] = _tmp; }   \
    } } while (0)

__device__ __forceinline__ void merge5_offsets(float t[KTOP])
{
    #pragma unroll
    for (int off = 16; off >= 4; off >>= 1) {
        float b0 = __shfl_xor_sync(0xffffffffu, t[0], off);
        float b1 = __shfl_xor_sync(0xffffffffu, t[1], off);
        float b2 = __shfl_xor_sync(0xffffffffu, t[2], off);
        float b3 = __shfl_xor_sync(0xffffffffu, t[3], off);
        float b4 = __shfl_xor_sync(0xffffffffu, t[4], off);
        float a0 = t[0], a1 = t[1], a2 = t[2], a3 = t[3], a4 = t[4];
        #pragma unroll
        for (int k = 0; k < KTOP; k++) {
            bool ta = a0 >= b0;
            t[k] = ta ? a0 : b0;
            if (ta) { a0 = a1; a1 = a2; a2 = a3; a3 = a4; a4 = -1e30f; }
            else    { b0 = b1; b1 = b2; b2 = b3; b3 = b4; b4 = -1e30f; }
        }
    }
}

// ---------------- kernel 3: register-blocked sims + top-5 ----------------
__global__ void __launch_bounds__(THREADS)
sim_kernel(int Q, int D)
{
    __shared__ float sq[QT * QSTRIDE];
    __shared__ float sd[DT * DSTRIDE];
    __shared__ float smerge[8][QT][KTOP];
    __shared__ int   scnt[8][QT];

    int a = blockIdx.y;
    int qbase = blockIdx.x * QT;
    const float* Aq = (a < 2) ? g_qN : g_qcN;
    const float* Bd = (a == 0) ? g_d1N : (a == 1) ? g_d2N
                    : (a == 2) ? g_d1cN : g_d2cN;

    int tid  = threadIdx.x;
    int qg   = tid & 3;
    int dth  = tid >> 2;
    int warp = tid >> 5;

    for (int i = tid; i < QT * 8; i += THREADS) {
        int r = i >> 3, ec = i & 7;
        int qq = qbase + r;
        float4 v = (qq < QMAX) ? *(const float4*)&Aq[(size_t)qq * QSTRIDE + ec * 4]
                               : make_float4(0.f, 0.f, 0.f, 0.f);
        *(float4*)&sq[r * QSTRIDE + ec * 4] = v;
    }

    float topk[4][KTOP];
    int cnt[4] = {0, 0, 0, 0};
    #pragma unroll
    for (int qi = 0; qi < 4; qi++)
        #pragma unroll
        for (int k = 0; k < KTOP; k++) topk[qi][k] = -1e30f;

    for (int dbase = 0; dbase < D; dbase += DT) {
        __syncthreads();
        for (int i = tid; i < DT * 8; i += THREADS) {
            int r = i >> 3, ec = i & 7;
            *(float4*)&sd[r * DSTRIDE + ec * 4] =
                *(const float4*)&Bd[(size_t)(dbase + r) * QSTRIDE + ec * 4];
        }
        __syncthreads();

        float acc[4][4];
        #pragma unroll
        for (int qi = 0; qi < 4; qi++)
            #pragma unroll
            for (int j = 0; j < 4; j++) acc[qi][j] = 0.f;

        #pragma unroll
        for (int ec = 0; ec < 8; ec++) {
            float4 dv0 = *(const float4*)&sd[(dth)       * DSTRIDE + ec * 4];
            float4 dv1 = *(const float4*)&sd[(dth +  64) * DSTRIDE + ec * 4];
            float4 dv2 = *(const float4*)&sd[(dth + 128) * DSTRIDE + ec * 4];
            float4 dv3 = *(const float4*)&sd[(dth + 192) * DSTRIDE + ec * 4];
            #pragma unroll
            for (int qi = 0; qi < 4; qi++) {
                float4 qv = *(const float4*)&sq[(qg * 4 + qi) * QSTRIDE + ec * 4];
                acc[qi][0] += qv.x * dv0.x + qv.y * dv0.y + qv.z * dv0.z + qv.w * dv0.w;
                acc[qi][1] += qv.x * dv1.x + qv.y * dv1.y + qv.z * dv1.z + qv.w * dv1.w;
                acc[qi][2] += qv.x * dv2.x + qv.y * dv2.y + qv.z * dv2.z + qv.w * dv2.w;
                acc[qi][3] += qv.x * dv3.x + qv.y * dv3.y + qv.z * dv3.z + qv.w * dv3.w;
            }
        }

        #pragma unroll
        for (int j = 0; j < 4; j++) {
            if (dbase + dth + j * 64 < D) {
                #pragma unroll
                for (int qi = 0; qi < 4; qi++) {
                    float s = acc[qi][j];
                    if (s > 0.999f) cnt[qi]++;
                    TOPK_INSERT(topk[qi], s);
                }
            }
        }
    }

    #pragma unroll
    for (int qi = 0; qi < 4; qi++) {
        merge5_offsets(topk[qi]);
        #pragma unroll
        for (int off = 16; off >= 4; off >>= 1)
            cnt[qi] += __shfl_xor_sync(0xffffffffu, cnt[qi], off);
    }
    int lane = tid & 31;
    if (lane < 4) {
        #pragma unroll
        for (int qi = 0; qi < 4; qi++) {
            int qrow = lane * 4 + qi;
            #pragma unroll
            for (int k = 0; k < KTOP; k++) smerge[warp][qrow][k] = topk[qi][k];
            scnt[warp][qrow] = cnt[qi];
        }
    }
    __syncthreads();

    if (tid < QT && qbase + tid < Q) {
        float t[KTOP];
        #pragma unroll
        for (int k = 0; k < KTOP; k++) t[k] = -1e30f;
        int c = 0;
        #pragma unroll
        for (int w = 0; w < 8; w++) {
            c += scnt[w][tid];
            #pragma unroll
            for (int k = 0; k < KTOP; k++) TOPK_INSERT(t, smerge[w][tid][k]);
        }
        float mean = (t[0] + t[1] + t[2] + t[3] + t[4]) * 0.2f;
        g_pool[a * QMAX + qbase + tid] = make_float2(t[0], mean);
        g_cnt4[a * QMAX + qbase + tid] = c;
    }
}

// ---------------- kernel 4: per-query MLP + reduction + scalars (256 thr) ----------------
__device__ __forceinline__ float mlp_out(const float temp[6],
                                         const float* __restrict__ Wq1,
                                         const float* __restrict__ Wq2)
{
    float out = 0.f;
    #pragma unroll
    for (int h = 0; h < 8; h++) {
        float hh = 0.f;
        #pragma unroll
        for (int j = 0; j < 6; j++) hh += __ldg(&Wq1[h * 6 + j]) * temp[j];
        out += __ldg(&Wq2[h]) * leaky(hh);
    }
    return out;
}

__global__ void __launch_bounds__(256)
combine_final_kernel(const float* __restrict__ Wq1,
                     const float* __restrict__ Wq2,
                     const float* __restrict__ gaf,
                     const float* __restrict__ baf,
                     const float* __restrict__ Wout,
                     float* __restrict__ out, int Q)
{
    __shared__ float r1[256], r2[256];
    int tid = threadIdx.x;
    float s1 = 0.f, s2 = 0.f;
    for (int q = tid; q < Q; q += 256) {
        float w = g_qw[q];
        {
            int c = g_cnt4[0 * QMAX + q];
            float2 pi = g_pool[0 * QMAX + q];
            float2 ps = g_pool[2 * QMAX + q];
            float temp[6] = { (c > 0) ? 1.f : 0.f, fminf((float)c, 5.f) * 0.2f,
                              pi.x, pi.y, ps.x, ps.y };
            s1 += mlp_out(temp, Wq1, Wq2) * w;
        }
        {
            int c = g_cnt4[1 * QMAX + q];
            float2 pi = g_pool[1 * QMAX + q];
            float2 ps = g_pool[3 * QMAX + q];
            float temp[6] = { (c > 0) ? 1.f : 0.f, fminf((float)c, 5.f) * 0.2f,
                              pi.x, pi.y, ps.x, ps.y };
            s2 += mlp_out(temp, Wq1, Wq2) * w;
        }
    }
    r1[tid] = s1; r2[tid] = s2; __syncthreads();
    for (int s = 128; s; s >>= 1) {
        if (tid < s) { r1[tid] += r1[tid + s]; r2[tid] += r2[tid + s]; }
        __syncthreads();
    }
    if (tid == 0) {
        float e1 = r1[0] / (float)Q;
        float e2 = r2[0] / (float)Q;
        float good = gaf[0] * Wout[0] + gaf[1] * Wout[1] + gaf[2] * Wout[2]
                   + gaf[3] * Wout[3] + e1 * Wout[4];
        float bad  = baf[0] * Wout[0] + baf[1] * Wout[1] + baf[2] * Wout[2]
                   + baf[3] * Wout[3] + e2 * Wout[4];
        float l = 1.f + bad - good;
        out[0] = (l > 0.f) ? l : 0.f;
        out[1] = good;
        out[2] = bad;
    }
}

// ---------------- launch ----------------
extern "C" void kernel_launch(void* const* d_in, const int* in_sizes, int n_in,
                              void* d_out, int out_size)
{
    const float* d1   = (const float*)d_in[0];
    const float* d2   = (const float*)d_in[1];
    const float* qe   = (const float*)d_in[2];
    const float* qidf = (const float*)d_in[3];
    const float* gaf  = (const float*)d_in[4];
    const float* baf  = (const float*)d_in[5];
    const float* Wc   = (const float*)d_in[6];
    const float* bc   = (const float*)d_in[7];
    const float* Wqw  = (const float*)d_in[8];
    const float* Wq1  = (const float*)d_in[9];
    const float* Wq2  = (const float*)d_in[10];
    const float* Wout = (const float*)d_in[11];

    int D = in_sizes[0] / EMB;
    int Q = in_sizes[2] / EMB;
    if (D > DMAX) D = DMAX;
    if (Q > QMAX) Q = QMAX;

    int totalRows = Q + 2 * D;
    int convWpb = 8;
    conv_kernel<<<(totalRows + convWpb - 1) / convWpb, convWpb * 32>>>(
        qe, d1, d2, qidf, Wc, bc, Wqw, Q, D);

    softmax_kernel<<<1, 256>>>(Q);

    dim3 simGrid((Q + QT - 1) / QT, 4);
    sim_kernel<<<simGrid, THREADS>>>(Q, D);

    combine_final_kernel<<<1, 256>>>(Wq1, Wq2, gaf, baf, Wout, (float*)d_out, Q);
}

// round 4
// speedup vs baseline: 2.4954x; 1.2048x over previous
#include <cuda_runtime.h>
#include <math.h>

#define EMB     30
#define KTOP    5
#define QMAX    2048
#define DMAX    8192
#define QT      16      // queries per sim block
#define DT      256     // docs per shared tile
#define THREADS 256
#define DSTRIDE 36      // doc tile row stride (floats)
#define QSTRIDE 32      // padded row stride of global operand matrices (floats)
#define CPART   8       // combine partial blocks

// ---------------- device scratch (static; zero-initialized) ----------------
__device__ float g_qN  [QMAX * QSTRIDE];
__device__ float g_qcN [QMAX * QSTRIDE];
__device__ float g_d1N [DMAX * QSTRIDE];
__device__ float g_d2N [DMAX * QSTRIDE];
__device__ float g_d1cN[DMAX * QSTRIDE];
__device__ float g_d2cN[DMAX * QSTRIDE];
__device__ float g_logits[QMAX];
__device__ float g_qw    [QMAX];
__device__ float2 g_pool [4 * QMAX];
__device__ int    g_cnt4 [4 * QMAX];
__device__ float2 g_part [CPART];

__device__ __forceinline__ float leaky(float x) { return x > 0.f ? x : 0.1f * x; }

// packed f32x2 FMA: acc.{lo,hi} += a.{lo,hi} * b.{lo,hi}
__device__ __forceinline__ void ffma2(unsigned long long& acc,
                                      unsigned long long a,
                                      unsigned long long b)
{
    asm("fma.rn.f32x2 %0, %1, %2, %0;" : "+l"(acc) : "l"(a), "l"(b));
}
__device__ __forceinline__ float hadd2(unsigned long long v)
{
    float lo = __uint_as_float((unsigned)(v & 0xffffffffULL));
    float hi = __uint_as_float((unsigned)(v >> 32));
    return lo + hi;
}

// ---------------- kernel 1: conv + residual + norms (weights in smem) ----------------
__global__ void __launch_bounds__(256)
conv_kernel(const float* __restrict__ qe,
            const float* __restrict__ d1,
            const float* __restrict__ d2,
            const float* __restrict__ qidf,
            const float* __restrict__ Wc,   // [30,30,3] = 2700
            const float* __restrict__ bc,   // [30]
            const float* __restrict__ Wqw,  // [31]
            int Q, int D)
{
    __shared__ float sWc[2700];
    __shared__ float sbc[30];
    __shared__ float sWqw[31];
    int tid = threadIdx.x;
    for (int i = tid; i < 2700; i += 256) sWc[i] = __ldg(&Wc[i]);
    if (tid < 30) sbc[tid] = __ldg(&bc[tid]);
    if (tid < 31) sWqw[tid] = __ldg(&Wqw[tid]);
    __syncthreads();

    int gw   = blockIdx.x * 8 + (tid >> 5);
    int lane = tid & 31;
    int total = Q + 2 * D;
    if (gw >= total) return;

    const float* x; float* yN; float* xN; int L, l, which;
    if (gw < Q)          { x = qe; yN = g_qcN;  xN = g_qN;  L = Q; l = gw;         which = 0; }
    else if (gw < Q + D) { x = d1; yN = g_d1cN; xN = g_d1N; L = D; l = gw - Q;     which = 1; }
    else                 { x = d2; yN = g_d2cN; xN = g_d2N; L = D; l = gw - Q - D; which = 2; }

    int o = lane;
    float yv = 0.f, xval = 0.f;
    if (o < EMB) {
        float acc = sbc[o];
        #pragma unroll
        for (int t = 0; t < 3; t++) {
            int ll = l + t - 1;
            if (ll >= 0 && ll < L) {
                const float* xr = x + (size_t)ll * EMB;
                #pragma unroll
                for (int i = 0; i < EMB; i++)
                    acc += __ldg(&xr[i]) * sWc[o * 90 + i * 3 + t];
            }
        }
        xval = __ldg(&x[(size_t)l * EMB + o]);
        yv = leaky(acc) + xval;
    }

    float s_conv = yv * yv;
    float s_orig = xval * xval;
    float lg = (which == 0 && o < EMB) ? yv * sWqw[o] : 0.f;
    #pragma unroll
    for (int off = 16; off; off >>= 1) {
        s_conv += __shfl_xor_sync(0xffffffffu, s_conv, off);
        s_orig += __shfl_xor_sync(0xffffffffu, s_orig, off);
        lg     += __shfl_xor_sync(0xffffffffu, lg,     off);
    }
    float ic = rsqrtf(s_conv);
    float io = rsqrtf(s_orig);
    yN[(size_t)l * QSTRIDE + o] = yv * ic;
    xN[(size_t)l * QSTRIDE + o] = xval * io;
    if (which == 0 && lane == 0)
        g_logits[l] = lg + __ldg(&qidf[l]) * sWqw[EMB];
}

// ---------------- kernel 2: softmax over Q logits ----------------
__global__ void __launch_bounds__(256)
softmax_kernel(int Q)
{
    __shared__ float red[256];
    int tid = threadIdx.x;
    float m = -1e30f;
    for (int i = tid; i < Q; i += 256) m = fmaxf(m, g_logits[i]);
    red[tid] = m; __syncthreads();
    for (int s = 128; s; s >>= 1) {
        if (tid < s) red[tid] = fmaxf(red[tid], red[tid + s]);
        __syncthreads();
    }
    float mx = red[0];
    __syncthreads();
    float sum = 0.f;
    for (int i = tid; i < Q; i += 256) sum += expf(g_logits[i] - mx);
    red[tid] = sum; __syncthreads();
    for (int s = 128; s; s >>= 1) {
        if (tid < s) red[tid] += red[tid + s];
        __syncthreads();
    }
    float inv = 1.f / red[0];
    for (int i = tid; i < Q; i += 256)
        g_qw[i] = expf(g_logits[i] - mx) * inv;
}

// ---------------- top-5 helpers ----------------
#define TOPK_INSERT(t, v) do {                                        \
    float _v = (v);                                                   \
    if (_v > t[4]) {                                                  \
        t[4] = _v; float _tmp;                                        \
        if (t[4] > t[3]) { _tmp = t[3]; t[3] = t[4]; t[4] = _tmp; }   \
        if (t[3] > t[2]) { _tmp = t[2]; t[2] = t[3]; t[3] = _tmp; }   \
        if (t[2] > t[1]) { _tmp = t[1]; t[1] = t[2]; t[2] = _tmp; }   \
        if (t[1] > t[0]) { _tmp = t[0]; t[0] = t[1]; t[1] = _tmp; }   \
    } } while (0)

__device__ __forceinline__ void merge5_offsets(float t[KTOP])
{
    #pragma unroll
    for (int off = 16; off >= 4; off >>= 1) {
        float b0 = __shfl_xor_sync(0xffffffffu, t[0], off);
        float b1 = __shfl_xor_sync(0xffffffffu, t[1], off);
        float b2 = __shfl_xor_sync(0xffffffffu, t[2], off);
        float b3 = __shfl_xor_sync(0xffffffffu, t[3], off);
        float b4 = __shfl_xor_sync(0xffffffffu, t[4], off);
        float a0 = t[0], a1 = t[1], a2 = t[2], a3 = t[3], a4 = t[4];
        #pragma unroll
        for (int k = 0; k < KTOP; k++) {
            bool ta = a0 >= b0;
            t[k] = ta ? a0 : b0;
            if (ta) { a0 = a1; a1 = a2; a2 = a3; a3 = a4; a4 = -1e30f; }
            else    { b0 = b1; b1 = b2; b2 = b3; b3 = b4; b4 = -1e30f; }
        }
    }
}

// ---------------- kernel 3: register-blocked sims (f32x2) + top-5 ----------------
__global__ void __launch_bounds__(THREADS)
sim_kernel(int Q, int D)
{
    __shared__ float sq[QT * QSTRIDE];
    __shared__ float sd[DT * DSTRIDE];
    __shared__ float smerge[8][QT][KTOP];
    __shared__ int   scnt[8][QT];

    int a = blockIdx.y;
    int qbase = blockIdx.x * QT;
    const float* Aq = (a < 2) ? g_qN : g_qcN;
    const float* Bd = (a == 0) ? g_d1N : (a == 1) ? g_d2N
                    : (a == 2) ? g_d1cN : g_d2cN;

    int tid  = threadIdx.x;
    int qg   = tid & 3;
    int dth  = tid >> 2;
    int warp = tid >> 5;

    for (int i = tid; i < QT * 8; i += THREADS) {
        int r = i >> 3, ec = i & 7;
        int qq = qbase + r;
        float4 v = (qq < QMAX) ? *(const float4*)&Aq[(size_t)qq * QSTRIDE + ec * 4]
                               : make_float4(0.f, 0.f, 0.f, 0.f);
        *(float4*)&sq[r * QSTRIDE + ec * 4] = v;
    }

    float topk[4][KTOP];
    int cnt[4] = {0, 0, 0, 0};
    #pragma unroll
    for (int qi = 0; qi < 4; qi++)
        #pragma unroll
        for (int k = 0; k < KTOP; k++) topk[qi][k] = -1e30f;

    for (int dbase = 0; dbase < D; dbase += DT) {
        __syncthreads();
        for (int i = tid; i < DT * 8; i += THREADS) {
            int r = i >> 3, ec = i & 7;
            *(float4*)&sd[r * DSTRIDE + ec * 4] =
                *(const float4*)&Bd[(size_t)(dbase + r) * QSTRIDE + ec * 4];
        }
        __syncthreads();

        unsigned long long acc2[4][4];
        #pragma unroll
        for (int qi = 0; qi < 4; qi++)
            #pragma unroll
            for (int j = 0; j < 4; j++) acc2[qi][j] = 0ULL;

        #pragma unroll
        for (int ec = 0; ec < 8; ec++) {
            ulonglong2 dv0 = *(const ulonglong2*)&sd[(dth)       * DSTRIDE + ec * 4];
            ulonglong2 dv1 = *(const ulonglong2*)&sd[(dth +  64) * DSTRIDE + ec * 4];
            ulonglong2 dv2 = *(const ulonglong2*)&sd[(dth + 128) * DSTRIDE + ec * 4];
            ulonglong2 dv3 = *(const ulonglong2*)&sd[(dth + 192) * DSTRIDE + ec * 4];
            #pragma unroll
            for (int qi = 0; qi < 4; qi++) {
                ulonglong2 qv = *(const ulonglong2*)&sq[(qg * 4 + qi) * QSTRIDE + ec * 4];
                ffma2(acc2[qi][0], qv.x, dv0.x);
                ffma2(acc2[qi][0], qv.y, dv0.y);
                ffma2(acc2[qi][1], qv.x, dv1.x);
                ffma2(acc2[qi][1], qv.y, dv1.y);
                ffma2(acc2[qi][2], qv.x, dv2.x);
                ffma2(acc2[qi][2], qv.y, dv2.y);
                ffma2(acc2[qi][3], qv.x, dv3.x);
                ffma2(acc2[qi][3], qv.y, dv3.y);
            }
        }

        #pragma unroll
        for (int j = 0; j < 4; j++) {
            if (dbase + dth + j * 64 < D) {
                #pragma unroll
                for (int qi = 0; qi < 4; qi++) {
                    float s = hadd2(acc2[qi][j]);
                    if (s > 0.999f) cnt[qi]++;
                    TOPK_INSERT(topk[qi], s);
                }
            }
        }
    }

    #pragma unroll
    for (int qi = 0; qi < 4; qi++) {
        merge5_offsets(topk[qi]);
        #pragma unroll
        for (int off = 16; off >= 4; off >>= 1)
            cnt[qi] += __shfl_xor_sync(0xffffffffu, cnt[qi], off);
    }
    int lane = tid & 31;
    if (lane < 4) {
        #pragma unroll
        for (int qi = 0; qi < 4; qi++) {
            int qrow = lane * 4 + qi;
            #pragma unroll
            for (int k = 0; k < KTOP; k++) smerge[warp][qrow][k] = topk[qi][k];
            scnt[warp][qrow] = cnt[qi];
        }
    }
    __syncthreads();

    if (tid < QT && qbase + tid < Q) {
        float t[KTOP];
        #pragma unroll
        for (int k = 0; k < KTOP; k++) t[k] = -1e30f;
        int c = 0;
        #pragma unroll
        for (int w = 0; w < 8; w++) {
            c += scnt[w][tid];
            #pragma unroll
            for (int k = 0; k < KTOP; k++) TOPK_INSERT(t, smerge[w][tid][k]);
        }
        float mean = (t[0] + t[1] + t[2] + t[3] + t[4]) * 0.2f;
        g_pool[a * QMAX + qbase + tid] = make_float2(t[0], mean);
        g_cnt4[a * QMAX + qbase + tid] = c;
    }
}

// ---------------- kernel 4a: per-query MLP partial sums (CPART blocks) ----------------
__device__ __forceinline__ float mlp_out(const float temp[6],
                                         const float* __restrict__ Wq1,
                                         const float* __restrict__ Wq2)
{
    float out = 0.f;
    #pragma unroll
    for (int h = 0; h < 8; h++) {
        float hh = 0.f;
        #pragma unroll
        for (int j = 0; j < 6; j++) hh += __ldg(&Wq1[h * 6 + j]) * temp[j];
        out += __ldg(&Wq2[h]) * leaky(hh);
    }
    return out;
}

__global__ void __launch_bounds__(256)
combine_partial_kernel(const float* __restrict__ Wq1,
                       const float* __restrict__ Wq2,
                       int Q)
{
    __shared__ float r1[256], r2[256];
    int tid = threadIdx.x;
    float s1 = 0.f, s2 = 0.f;
    for (int q = blockIdx.x * 256 + tid; q < Q; q += CPART * 256) {
        float w = g_qw[q];
        {
            int c = g_cnt4[0 * QMAX + q];
            float2 pi = g_pool[0 * QMAX + q];
            float2 ps = g_pool[2 * QMAX + q];
            float temp[6] = { (c > 0) ? 1.f : 0.f, fminf((float)c, 5.f) * 0.2f,
                              pi.x, pi.y, ps.x, ps.y };
            s1 += mlp_out(temp, Wq1, Wq2) * w;
        }
        {
            int c = g_cnt4[1 * QMAX + q];
            float2 pi = g_pool[1 * QMAX + q];
            float2 ps = g_pool[3 * QMAX + q];
            float temp[6] = { (c > 0) ? 1.f : 0.f, fminf((float)c, 5.f) * 0.2f,
                              pi.x, pi.y, ps.x, ps.y };
            s2 += mlp_out(temp, Wq1, Wq2) * w;
        }
    }
    r1[tid] = s1; r2[tid] = s2; __syncthreads();
    for (int s = 128; s; s >>= 1) {
        if (tid < s) { r1[tid] += r1[tid + s]; r2[tid] += r2[tid + s]; }
        __syncthreads();
    }
    if (tid == 0) g_part[blockIdx.x] = make_float2(r1[0], r2[0]);
}

// ---------------- kernel 4b: finalize ----------------
__global__ void final_kernel(const float* __restrict__ gaf,
                             const float* __restrict__ baf,
                             const float* __restrict__ Wout,
                             float* __restrict__ out, int Q)
{
    if (threadIdx.x == 0) {
        float s1 = 0.f, s2 = 0.f;
        #pragma unroll
        for (int b = 0; b < CPART; b++) { s1 += g_part[b].x; s2 += g_part[b].y; }
        float e1 = s1 / (float)Q;
        float e2 = s2 / (float)Q;
        float good = gaf[0] * Wout[0] + gaf[1] * Wout[1] + gaf[2] * Wout[2]
                   + gaf[3] * Wout[3] + e1 * Wout[4];
        float bad  = baf[0] * Wout[0] + baf[1] * Wout[1] + baf[2] * Wout[2]
                   + baf[3] * Wout[3] + e2 * Wout[4];
        float l = 1.f + bad - good;
        out[0] = (l > 0.f) ? l : 0.f;
        out[1] = good;
        out[2] = bad;
    }
}

// ---------------- launch ----------------
extern "C" void kernel_launch(void* const* d_in, const int* in_sizes, int n_in,
                              void* d_out, int out_size)
{
    const float* d1   = (const float*)d_in[0];
    const float* d2   = (const float*)d_in[1];
    const float* qe   = (const float*)d_in[2];
    const float* qidf = (const float*)d_in[3];
    const float* gaf  = (const float*)d_in[4];
    const float* baf  = (const float*)d_in[5];
    const float* Wc   = (const float*)d_in[6];
    const float* bc   = (const float*)d_in[7];
    const float* Wqw  = (const float*)d_in[8];
    const float* Wq1  = (const float*)d_in[9];
    const float* Wq2  = (const float*)d_in[10];
    const float* Wout = (const float*)d_in[11];

    int D = in_sizes[0] / EMB;
    int Q = in_sizes[2] / EMB;
    if (D > DMAX) D = DMAX;
    if (Q > QMAX) Q = QMAX;

    int totalRows = Q + 2 * D;
    conv_kernel<<<(totalRows + 7) / 8, 256>>>(qe, d1, d2, qidf, Wc, bc, Wqw, Q, D);

    softmax_kernel<<<1, 256>>>(Q);

    dim3 simGrid((Q + QT - 1) / QT, 4);
    sim_kernel<<<simGrid, THREADS>>>(Q, D);

    combine_partial_kernel<<<CPART, 256>>>(Wq1, Wq2, Q);
    final_kernel<<<1, 32>>>(gaf, baf, Wout, (float*)d_out, Q);
}

// round 5
// speedup vs baseline: 3.5037x; 1.4041x over previous
#include <cuda_runtime.h>
#include <math.h>

#define EMB     30
#define KTOP    5
#define QMAX    2048
#define DMAX    8192
#define QT      16      // queries per sim block
#define DT      256     // docs per shared tile
#define THREADS 256
#define DSTRIDE 36      // doc tile row stride (floats); 16B-aligned, conflict-min
#define QSTRIDE 32      // padded row stride of global operand matrices (floats)
#define CPART   8       // combine partial blocks

// ---------------- device scratch (static; zero-initialized) ----------------
__device__ float g_qN  [QMAX * QSTRIDE];
__device__ float g_qcN [QMAX * QSTRIDE];
__device__ float g_d1N [DMAX * QSTRIDE];
__device__ float g_d2N [DMAX * QSTRIDE];
__device__ float g_d1cN[DMAX * QSTRIDE];
__device__ float g_d2cN[DMAX * QSTRIDE];
__device__ float g_logits[QMAX];
__device__ float g_qw    [QMAX];
__device__ float2 g_pool [4 * QMAX];
__device__ int    g_cnt4 [4 * QMAX];
__device__ float2 g_part [CPART];

__device__ __forceinline__ float leaky(float x) { return x > 0.f ? x : 0.1f * x; }

// packed f32x2 FMA: acc.{lo,hi} += a.{lo,hi} * b.{lo,hi}
__device__ __forceinline__ void ffma2(unsigned long long& acc,
                                      unsigned long long a,
                                      unsigned long long b)
{
    asm("fma.rn.f32x2 %0, %1, %2, %0;" : "+l"(acc) : "l"(a), "l"(b));
}
__device__ __forceinline__ float hadd2(unsigned long long v)
{
    float lo = __uint_as_float((unsigned)(v & 0xffffffffULL));
    float hi = __uint_as_float((unsigned)(v >> 32));
    return lo + hi;
}

// ---------------- kernel 1: conv + residual + norms (grid-stride, weights staged once) ----
__global__ void __launch_bounds__(256)
conv_kernel(const float* __restrict__ qe,
            const float* __restrict__ d1,
            const float* __restrict__ d2,
            const float* __restrict__ qidf,
            const float* __restrict__ Wc,   // [30,30,3] = 2700
            const float* __restrict__ bc,   // [30]
            const float* __restrict__ Wqw,  // [31]
            int Q, int D)
{
    __shared__ float sWc[2700];
    __shared__ float sbc[30];
    __shared__ float sWqw[31];
    int tid = threadIdx.x;
    for (int i = tid; i < 2700; i += 256) sWc[i] = __ldg(&Wc[i]);
    if (tid < 30) sbc[tid] = __ldg(&bc[tid]);
    if (tid < 31) sWqw[tid] = __ldg(&Wqw[tid]);
    __syncthreads();

    int warp = tid >> 5;
    int lane = tid & 31;
    int total  = Q + 2 * D;
    int groups = (total + 7) >> 3;

    for (int g = blockIdx.x; g < groups; g += gridDim.x) {
        int gw = g * 8 + warp;
        if (gw >= total) continue;

        const float* x; float* yN; float* xN; int L, l, which;
        if (gw < Q)          { x = qe; yN = g_qcN;  xN = g_qN;  L = Q; l = gw;         which = 0; }
        else if (gw < Q + D) { x = d1; yN = g_d1cN; xN = g_d1N; L = D; l = gw - Q;     which = 1; }
        else                 { x = d2; yN = g_d2cN; xN = g_d2N; L = D; l = gw - Q - D; which = 2; }

        int o = lane;
        float yv = 0.f, xval = 0.f;
        if (o < EMB) {
            float acc = sbc[o];
            #pragma unroll
            for (int t = 0; t < 3; t++) {
                int ll = l + t - 1;
                if (ll >= 0 && ll < L) {
                    const float* xr = x + (size_t)ll * EMB;
                    #pragma unroll
                    for (int i = 0; i < EMB; i++)
                        acc += __ldg(&xr[i]) * sWc[o * 90 + i * 3 + t];
                }
            }
            xval = __ldg(&x[(size_t)l * EMB + o]);
            yv = leaky(acc) + xval;
        }

        float s_conv = yv * yv;
        float s_orig = xval * xval;
        float lg = (which == 0 && o < EMB) ? yv * sWqw[o] : 0.f;
        #pragma unroll
        for (int off = 16; off; off >>= 1) {
            s_conv += __shfl_xor_sync(0xffffffffu, s_conv, off);
            s_orig += __shfl_xor_sync(0xffffffffu, s_orig, off);
            lg     += __shfl_xor_sync(0xffffffffu, lg,     off);
        }
        float ic = rsqrtf(s_conv);
        float io = rsqrtf(s_orig);
        yN[(size_t)l * QSTRIDE + o] = yv * ic;
        xN[(size_t)l * QSTRIDE + o] = xval * io;
        if (which == 0 && lane == 0)
            g_logits[l] = lg + __ldg(&qidf[l]) * sWqw[EMB];
    }
}

// ---------------- kernel 2: softmax over Q logits ----------------
__global__ void __launch_bounds__(256)
softmax_kernel(int Q)
{
    __shared__ float red[256];
    int tid = threadIdx.x;
    float m = -1e30f;
    for (int i = tid; i < Q; i += 256) m = fmaxf(m, g_logits[i]);
    red[tid] = m; __syncthreads();
    for (int s = 128; s; s >>= 1) {
        if (tid < s) red[tid] = fmaxf(red[tid], red[tid + s]);
        __syncthreads();
    }
    float mx = red[0];
    __syncthreads();
    float sum = 0.f;
    for (int i = tid; i < Q; i += 256) sum += expf(g_logits[i] - mx);
    red[tid] = sum; __syncthreads();
    for (int s = 128; s; s >>= 1) {
        if (tid < s) red[tid] += red[tid + s];
        __syncthreads();
    }
    float inv = 1.f / red[0];
    for (int i = tid; i < Q; i += 256)
        g_qw[i] = expf(g_logits[i] - mx) * inv;
}

// ---------------- top-5 helpers ----------------
#define TOPK_INSERT(t, v) do {                                        \
    float _v = (v);                                                   \
    if (_v > t[4]) {                                                  \
        t[4] = _v; float _tmp;                                        \
        if (t[4] > t[3]) { _tmp = t[3]; t[3] = t[4]; t[4] = _tmp; }   \
        if (t[3] > t[2]) { _tmp = t[2]; t[2] = t[3]; t[3] = _tmp; }   \
        if (t[2] > t[1]) { _tmp = t[1]; t[1] = t[2]; t[2] = _tmp; }   \
        if (t[1] > t[0]) { _tmp = t[0]; t[0] = t[1]; t[1] = _tmp; }   \
    } } while (0)

// full-warp merge of sorted-5 lists (offsets 16..1)
__device__ __forceinline__ void merge5_warp(float t[KTOP])
{
    #pragma unroll
    for (int off = 16; off >= 1; off >>= 1) {
        float b0 = __shfl_xor_sync(0xffffffffu, t[0], off);
        float b1 = __shfl_xor_sync(0xffffffffu, t[1], off);
        float b2 = __shfl_xor_sync(0xffffffffu, t[2], off);
        float b3 = __shfl_xor_sync(0xffffffffu, t[3], off);
        float b4 = __shfl_xor_sync(0xffffffffu, t[4], off);
        float a0 = t[0], a1 = t[1], a2 = t[2], a3 = t[3], a4 = t[4];
        #pragma unroll
        for (int k = 0; k < KTOP; k++) {
            bool ta = a0 >= b0;
            t[k] = ta ? a0 : b0;
            if (ta) { a0 = a1; a1 = a2; a2 = a3; a3 = a4; a4 = -1e30f; }
            else    { b0 = b1; b1 = b2; b2 = b3; b3 = b4; b4 = -1e30f; }
        }
    }
}

// ---------------- kernel 3: sims, broadcast query LDS + register prefetch ----------------
__global__ void __launch_bounds__(THREADS)
sim_kernel(int Q, int D)
{
    __shared__ float sq[QT * QSTRIDE];      // 2 KB
    __shared__ float sd[DT * DSTRIDE];      // 36 KB
    __shared__ float smerge[8][4][KTOP];
    __shared__ int   scnt[8][4];

    int a = blockIdx.y;
    int qbase = blockIdx.x * QT;
    const float* Aq = (a < 2) ? g_qN : g_qcN;
    const float* Bd = (a == 0) ? g_d1N : (a == 1) ? g_d2N
                    : (a == 2) ? g_d1cN : g_d2cN;

    int tid  = threadIdx.x;
    int warp = tid >> 5;
    int lane = tid & 31;
    int qg   = tid >> 6;       // 0..3 — uniform within a warp (broadcast query loads)
    int dth  = tid & 63;       // 0..63 — 32 consecutive rows per warp

    // stage query tile
    for (int i = tid; i < QT * 8; i += THREADS) {
        int r = i >> 3, ec = i & 7;
        int qq = qbase + r;
        float4 v = (qq < QMAX) ? *(const float4*)&Aq[(size_t)qq * QSTRIDE + ec * 4]
                               : make_float4(0.f, 0.f, 0.f, 0.f);
        *(float4*)&sq[r * QSTRIDE + ec * 4] = v;
    }

    float topk[4][KTOP];
    int cnt[4] = {0, 0, 0, 0};
    #pragma unroll
    for (int qi = 0; qi < 4; qi++)
        #pragma unroll
        for (int k = 0; k < KTOP; k++) topk[qi][k] = -1e30f;

    int ntiles = (D + DT - 1) / DT;

    // prefetch tile 0 into registers (8 float4 per thread)
    float4 pf[8];
    #pragma unroll
    for (int k = 0; k < 8; k++) {
        int i = tid + k * THREADS;
        int r = i >> 3, ec = i & 7;
        pf[k] = *(const float4*)&Bd[(size_t)r * QSTRIDE + ec * 4];
    }

    for (int t = 0; t < ntiles; t++) {
        __syncthreads();   // previous tile's compute (and sq staging) done
        #pragma unroll
        for (int k = 0; k < 8; k++) {
            int i = tid + k * THREADS;
            int r = i >> 3, ec = i & 7;
            *(float4*)&sd[r * DSTRIDE + ec * 4] = pf[k];
        }
        __syncthreads();

        // issue next tile's loads early (latency hidden under compute)
        if (t + 1 < ntiles) {
            int dnext = (t + 1) * DT;
            #pragma unroll
            for (int k = 0; k < 8; k++) {
                int i = tid + k * THREADS;
                int r = i >> 3, ec = i & 7;
                pf[k] = *(const float4*)&Bd[(size_t)(dnext + r) * QSTRIDE + ec * 4];
            }
        }

        unsigned long long acc2[4][4];
        #pragma unroll
        for (int qi = 0; qi < 4; qi++)
            #pragma unroll
            for (int j = 0; j < 4; j++) acc2[qi][j] = 0ULL;

        #pragma unroll
        for (int ec = 0; ec < 8; ec++) {
            ulonglong2 dv0 = *(const ulonglong2*)&sd[(dth)       * DSTRIDE + ec * 4];
            ulonglong2 dv1 = *(const ulonglong2*)&sd[(dth +  64) * DSTRIDE + ec * 4];
            ulonglong2 dv2 = *(const ulonglong2*)&sd[(dth + 128) * DSTRIDE + ec * 4];
            ulonglong2 dv3 = *(const ulonglong2*)&sd[(dth + 192) * DSTRIDE + ec * 4];
            #pragma unroll
            for (int qi = 0; qi < 4; qi++) {
                ulonglong2 qv = *(const ulonglong2*)&sq[(qg * 4 + qi) * QSTRIDE + ec * 4];
                ffma2(acc2[qi][0], qv.x, dv0.x);
                ffma2(acc2[qi][0], qv.y, dv0.y);
                ffma2(acc2[qi][1], qv.x, dv1.x);
                ffma2(acc2[qi][1], qv.y, dv1.y);
                ffma2(acc2[qi][2], qv.x, dv2.x);
                ffma2(acc2[qi][2], qv.y, dv2.y);
                ffma2(acc2[qi][3], qv.x, dv3.x);
                ffma2(acc2[qi][3], qv.y, dv3.y);
            }
        }

        int dbase = t * DT;
        #pragma unroll
        for (int j = 0; j < 4; j++) {
            if (dbase + dth + j * 64 < D) {
                #pragma unroll
                for (int qi = 0; qi < 4; qi++) {
                    float s = hadd2(acc2[qi][j]);
                    if (s > 0.999f) cnt[qi]++;
                    TOPK_INSERT(topk[qi], s);
                }
            }
        }
    }

    // full-warp merge: all 32 lanes of this warp hold partials for the same 4 queries
    #pragma unroll
    for (int qi = 0; qi < 4; qi++) {
        merge5_warp(topk[qi]);
        #pragma unroll
        for (int off = 16; off >= 1; off >>= 1)
            cnt[qi] += __shfl_xor_sync(0xffffffffu, cnt[qi], off);
    }
    if (lane == 0) {
        #pragma unroll
        for (int qi = 0; qi < 4; qi++) {
            #pragma unroll
            for (int k = 0; k < KTOP; k++) smerge[warp][qi][k] = topk[qi][k];
            scnt[warp][qi] = cnt[qi];
        }
    }
    __syncthreads();

    // final: merge the 2 warps of each query group; one thread per query
    if (tid < QT && qbase + tid < Q) {
        int qg2 = tid >> 2, qi = tid & 3;
        int w0 = 2 * qg2, w1 = 2 * qg2 + 1;
        float A0 = smerge[w0][qi][0], A1 = smerge[w0][qi][1], A2 = smerge[w0][qi][2],
              A3 = smerge[w0][qi][3], A4 = smerge[w0][qi][4];
        float B0 = smerge[w1][qi][0], B1 = smerge[w1][qi][1], B2 = smerge[w1][qi][2],
              B3 = smerge[w1][qi][3], B4 = smerge[w1][qi][4];
        float t5[KTOP];
        #pragma unroll
        for (int k = 0; k < KTOP; k++) {
            bool ta = A0 >= B0;
            t5[k] = ta ? A0 : B0;
            if (ta) { A0 = A1; A1 = A2; A2 = A3; A3 = A4; A4 = -1e30f; }
            else    { B0 = B1; B1 = B2; B2 = B3; B3 = B4; B4 = -1e30f; }
        }
        int c = scnt[w0][qi] + scnt[w1][qi];
        float mean = (t5[0] + t5[1] + t5[2] + t5[3] + t5[4]) * 0.2f;
        g_pool[a * QMAX + qbase + tid] = make_float2(t5[0], mean);
        g_cnt4[a * QMAX + qbase + tid] = c;
    }
}

// ---------------- kernel 4a: per-query MLP partial sums ----------------
__device__ __forceinline__ float mlp_out(const float temp[6],
                                         const float* __restrict__ Wq1,
                                         const float* __restrict__ Wq2)
{
    float out = 0.f;
    #pragma unroll
    for (int h = 0; h < 8; h++) {
        float hh = 0.f;
        #pragma unroll
        for (int j = 0; j < 6; j++) hh += __ldg(&Wq1[h * 6 + j]) * temp[j];
        out += __ldg(&Wq2[h]) * leaky(hh);
    }
    return out;
}

__global__ void __launch_bounds__(256)
combine_partial_kernel(const float* __restrict__ Wq1,
                       const float* __restrict__ Wq2,
                       int Q)
{
    __shared__ float r1[256], r2[256];
    int tid = threadIdx.x;
    float s1 = 0.f, s2 = 0.f;
    for (int q = blockIdx.x * 256 + tid; q < Q; q += CPART * 256) {
        float w = g_qw[q];
        {
            int c = g_cnt4[0 * QMAX + q];
            float2 pi = g_pool[0 * QMAX + q];
            float2 ps = g_pool[2 * QMAX + q];
            float temp[6] = { (c > 0) ? 1.f : 0.f, fminf((float)c, 5.f) * 0.2f,
                              pi.x, pi.y, ps.x, ps.y };
            s1 += mlp_out(temp, Wq1, Wq2) * w;
        }
        {
            int c = g_cnt4[1 * QMAX + q];
            float2 pi = g_pool[1 * QMAX + q];
            float2 ps = g_pool[3 * QMAX + q];
            float temp[6] = { (c > 0) ? 1.f : 0.f, fminf((float)c, 5.f) * 0.2f,
                              pi.x, pi.y, ps.x, ps.y };
            s2 += mlp_out(temp, Wq1, Wq2) * w;
        }
    }
    r1[tid] = s1; r2[tid] = s2; __syncthreads();
    for (int s = 128; s; s >>= 1) {
        if (tid < s) { r1[tid] += r1[tid + s]; r2[tid] += r2[tid + s]; }
        __syncthreads();
    }
    if (tid == 0) g_part[blockIdx.x] = make_float2(r1[0], r2[0]);
}

// ---------------- kernel 4b: finalize ----------------
__global__ void final_kernel(const float* __restrict__ gaf,
                             const float* __restrict__ baf,
                             const float* __restrict__ Wout,
                             float* __restrict__ out, int Q)
{
    if (threadIdx.x == 0) {
        float s1 = 0.f, s2 = 0.f;
        #pragma unroll
        for (int b = 0; b < CPART; b++) { s1 += g_part[b].x; s2 += g_part[b].y; }
        float e1 = s1 / (float)Q;
        float e2 = s2 / (float)Q;
        float good = gaf[0] * Wout[0] + gaf[1] * Wout[1] + gaf[2] * Wout[2]
                   + gaf[3] * Wout[3] + e1 * Wout[4];
        float bad  = baf[0] * Wout[0] + baf[1] * Wout[1] + baf[2] * Wout[2]
                   + baf[3] * Wout[3] + e2 * Wout[4];
        float l = 1.f + bad - good;
        out[0] = (l > 0.f) ? l : 0.f;
        out[1] = good;
        out[2] = bad;
    }
}

// ---------------- launch ----------------
extern "C" void kernel_launch(void* const* d_in, const int* in_sizes, int n_in,
                              void* d_out, int out_size)
{
    const float* d1   = (const float*)d_in[0];
    const float* d2   = (const float*)d_in[1];
    const float* qe   = (const float*)d_in[2];
    const float* qidf = (const float*)d_in[3];
    const float* gaf  = (const float*)d_in[4];
    const float* baf  = (const float*)d_in[5];
    const float* Wc   = (const float*)d_in[6];
    const float* bc   = (const float*)d_in[7];
    const float* Wqw  = (const float*)d_in[8];
    const float* Wq1  = (const float*)d_in[9];
    const float* Wq2  = (const float*)d_in[10];
    const float* Wout = (const float*)d_in[11];

    int D = in_sizes[0] / EMB;
    int Q = in_sizes[2] / EMB;
    if (D > DMAX) D = DMAX;
    if (Q > QMAX) Q = QMAX;

    int totalRows = Q + 2 * D;
    int groups = (totalRows + 7) / 8;
    int convBlocks = groups < 1184 ? groups : 1184;
    conv_kernel<<<convBlocks, 256>>>(qe, d1, d2, qidf, Wc, bc, Wqw, Q, D);

    softmax_kernel<<<1, 256>>>(Q);

    dim3 simGrid((Q + QT - 1) / QT, 4);
    sim_kernel<<<simGrid, THREADS>>>(Q, D);

    combine_partial_kernel<<<CPART, 256>>>(Wq1, Wq2, Q);
    final_kernel<<<1, 32>>>(gaf, baf, Wout, (float*)d_out, Q);
}

// round 6
// speedup vs baseline: 3.7092x; 1.0586x over previous
#include <cuda_runtime.h>
#include <math.h>

#define EMB     30
#define KTOP    5
#define QMAX    2048
#define DMAX    8192
#define QT      32      // queries per sim block (8 per query-group)
#define QPG     8       // queries per group
#define DT      128     // docs per shared tile
#define THREADS 256
#define DSTRIDE 36      // doc tile row stride (floats)
#define QSTRIDE 32      // padded row stride of global operand matrices (floats)
#define CPART   8       // combine partial blocks

// ---------------- device scratch (static; zero-initialized) ----------------
__device__ float g_qN  [QMAX * QSTRIDE];
__device__ float g_qcN [QMAX * QSTRIDE];
__device__ float g_d1N [DMAX * QSTRIDE];
__device__ float g_d2N [DMAX * QSTRIDE];
__device__ float g_d1cN[DMAX * QSTRIDE];
__device__ float g_d2cN[DMAX * QSTRIDE];
__device__ float g_logits[QMAX];
__device__ float g_qw    [QMAX];
__device__ float2 g_pool [4 * QMAX];
__device__ int    g_cnt4 [4 * QMAX];
__device__ float2 g_part [CPART];

__device__ __forceinline__ float leaky(float x) { return x > 0.f ? x : 0.1f * x; }

__device__ __forceinline__ void ffma2(unsigned long long& acc,
                                      unsigned long long a,
                                      unsigned long long b)
{
    asm("fma.rn.f32x2 %0, %1, %2, %0;" : "+l"(acc) : "l"(a), "l"(b));
}
__device__ __forceinline__ float hadd2(unsigned long long v)
{
    float lo = __uint_as_float((unsigned)(v & 0xffffffffULL));
    float hi = __uint_as_float((unsigned)(v >> 32));
    return lo + hi;
}

// ---------------- kernel 1: conv + residual + norms ----------------
__global__ void __launch_bounds__(256)
conv_kernel(const float* __restrict__ qe,
            const float* __restrict__ d1,
            const float* __restrict__ d2,
            const float* __restrict__ qidf,
            const float* __restrict__ Wc,   // [30,30,3] = 2700
            const float* __restrict__ bc,   // [30]
            const float* __restrict__ Wqw,  // [31]
            int Q, int D)
{
    __shared__ float sWc[2700];
    __shared__ float sbc[30];
    __shared__ float sWqw[31];
    int tid = threadIdx.x;
    for (int i = tid; i < 2700; i += 256) sWc[i] = __ldg(&Wc[i]);
    if (tid < 30) sbc[tid] = __ldg(&bc[tid]);
    if (tid < 31) sWqw[tid] = __ldg(&Wqw[tid]);
    __syncthreads();

    int warp = tid >> 5;
    int lane = tid & 31;
    int total  = Q + 2 * D;
    int groups = (total + 7) >> 3;

    for (int g = blockIdx.x; g < groups; g += gridDim.x) {
        int gw = g * 8 + warp;
        if (gw >= total) continue;

        const float* x; float* yN; float* xN; int L, l, which;
        if (gw < Q)          { x = qe; yN = g_qcN;  xN = g_qN;  L = Q; l = gw;         which = 0; }
        else if (gw < Q + D) { x = d1; yN = g_d1cN; xN = g_d1N; L = D; l = gw - Q;     which = 1; }
        else                 { x = d2; yN = g_d2cN; xN = g_d2N; L = D; l = gw - Q - D; which = 2; }

        int o = lane;
        float yv = 0.f, xval = 0.f;
        if (o < EMB) {
            float acc = sbc[o];
            #pragma unroll
            for (int t = 0; t < 3; t++) {
                int ll = l + t - 1;
                if (ll >= 0 && ll < L) {
                    const float* xr = x + (size_t)ll * EMB;
                    #pragma unroll
                    for (int i = 0; i < EMB; i++)
                        acc += __ldg(&xr[i]) * sWc[o * 90 + i * 3 + t];
                }
            }
            xval = __ldg(&x[(size_t)l * EMB + o]);
            yv = leaky(acc) + xval;
        }

        float s_conv = yv * yv;
        float s_orig = xval * xval;
        float lg = (which == 0 && o < EMB) ? yv * sWqw[o] : 0.f;
        #pragma unroll
        for (int off = 16; off; off >>= 1) {
            s_conv += __shfl_xor_sync(0xffffffffu, s_conv, off);
            s_orig += __shfl_xor_sync(0xffffffffu, s_orig, off);
            lg     += __shfl_xor_sync(0xffffffffu, lg,     off);
        }
        float ic = rsqrtf(s_conv);
        float io = rsqrtf(s_orig);
        yN[(size_t)l * QSTRIDE + o] = yv * ic;
        xN[(size_t)l * QSTRIDE + o] = xval * io;
        if (which == 0 && lane == 0)
            g_logits[l] = lg + __ldg(&qidf[l]) * sWqw[EMB];
    }
}

// ---------------- kernel 2: softmax over Q logits ----------------
__global__ void __launch_bounds__(256)
softmax_kernel(int Q)
{
    __shared__ float red[256];
    int tid = threadIdx.x;
    float m = -1e30f;
    for (int i = tid; i < Q; i += 256) m = fmaxf(m, g_logits[i]);
    red[tid] = m; __syncthreads();
    for (int s = 128; s; s >>= 1) {
        if (tid < s) red[tid] = fmaxf(red[tid], red[tid + s]);
        __syncthreads();
    }
    float mx = red[0];
    __syncthreads();
    float sum = 0.f;
    for (int i = tid; i < Q; i += 256) sum += expf(g_logits[i] - mx);
    red[tid] = sum; __syncthreads();
    for (int s = 128; s; s >>= 1) {
        if (tid < s) red[tid] += red[tid + s];
        __syncthreads();
    }
    float inv = 1.f / red[0];
    for (int i = tid; i < Q; i += 256)
        g_qw[i] = expf(g_logits[i] - mx) * inv;
}

// ---------------- top-5 helpers ----------------
#define TOPK_INSERT(t, v) do {                                        \
    float _v = (v);                                                   \
    if (_v > t[4]) {                                                  \
        t[4] = _v; float _tmp;                                        \
        if (t[4] > t[3]) { _tmp = t[3]; t[3] = t[4]; t[4] = _tmp; }   \
        if (t[3] > t[2]) { _tmp = t[2]; t[2] = t[3]; t[3] = _tmp; }   \
        if (t[2] > t[1]) { _tmp = t[1]; t[1] = t[2]; t[2] = _tmp; }   \
        if (t[1] > t[0]) { _tmp = t[0]; t[0] = t[1]; t[1] = _tmp; }   \
    } } while (0)

__device__ __forceinline__ void merge5_warp(float t[KTOP])
{
    #pragma unroll
    for (int off = 16; off >= 1; off >>= 1) {
        float b0 = __shfl_xor_sync(0xffffffffu, t[0], off);
        float b1 = __shfl_xor_sync(0xffffffffu, t[1], off);
        float b2 = __shfl_xor_sync(0xffffffffu, t[2], off);
        float b3 = __shfl_xor_sync(0xffffffffu, t[3], off);
        float b4 = __shfl_xor_sync(0xffffffffu, t[4], off);
        float a0 = t[0], a1 = t[1], a2 = t[2], a3 = t[3], a4 = t[4];
        #pragma unroll
        for (int k = 0; k < KTOP; k++) {
            bool ta = a0 >= b0;
            t[k] = ta ? a0 : b0;
            if (ta) { a0 = a1; a1 = a2; a2 = a3; a3 = a4; a4 = -1e30f; }
            else    { b0 = b1; b1 = b2; b2 = b3; b3 = b4; b4 = -1e30f; }
        }
    }
}

// ---------------- kernel 3: sims, 8 queries/group, broadcast LDS + prefetch ------------
__global__ void __launch_bounds__(THREADS, 1)
sim_kernel(int Q, int D)
{
    __shared__ float sq[QT * QSTRIDE];        // 4 KB
    __shared__ float sd[DT * DSTRIDE];        // 18 KB
    __shared__ float smerge[8][QPG][KTOP];
    __shared__ int   scnt[8][QPG];

    int a = blockIdx.y;
    int qbase = blockIdx.x * QT;
    const float* Aq = (a < 2) ? g_qN : g_qcN;
    const float* Bd = (a == 0) ? g_d1N : (a == 1) ? g_d2N
                    : (a == 2) ? g_d1cN : g_d2cN;

    int tid  = threadIdx.x;
    int warp = tid >> 5;
    int lane = tid & 31;
    int qg   = tid >> 6;       // 0..3 — uniform within warp
    int dth  = tid & 63;       // 0..63

    // stage query tile: 32 rows x 8 float4 = 256 float4, one per thread
    {
        int r = tid >> 3, ec = tid & 7;
        int qq = qbase + r;
        float4 v = (qq < QMAX) ? *(const float4*)&Aq[(size_t)qq * QSTRIDE + ec * 4]
                               : make_float4(0.f, 0.f, 0.f, 0.f);
        *(float4*)&sq[r * QSTRIDE + ec * 4] = v;
    }

    float topk[QPG][KTOP];
    int cnt[QPG];
    #pragma unroll
    for (int qi = 0; qi < QPG; qi++) {
        cnt[qi] = 0;
        #pragma unroll
        for (int k = 0; k < KTOP; k++) topk[qi][k] = -1e30f;
    }

    int ntiles = (D + DT - 1) / DT;

    // prefetch tile 0 (4 float4 per thread)
    float4 pf[4];
    #pragma unroll
    for (int k = 0; k < 4; k++) {
        int i = tid + k * THREADS;
        int r = i >> 3, ec = i & 7;
        pf[k] = *(const float4*)&Bd[(size_t)r * QSTRIDE + ec * 4];
    }

    for (int t = 0; t < ntiles; t++) {
        __syncthreads();
        #pragma unroll
        for (int k = 0; k < 4; k++) {
            int i = tid + k * THREADS;
            int r = i >> 3, ec = i & 7;
            *(float4*)&sd[r * DSTRIDE + ec * 4] = pf[k];
        }
        __syncthreads();

        if (t + 1 < ntiles) {
            int dnext = (t + 1) * DT;
            #pragma unroll
            for (int k = 0; k < 4; k++) {
                int i = tid + k * THREADS;
                int r = i >> 3, ec = i & 7;
                pf[k] = *(const float4*)&Bd[(size_t)(dnext + r) * QSTRIDE + ec * 4];
            }
        }

        unsigned long long acc2[QPG][2];
        #pragma unroll
        for (int qi = 0; qi < QPG; qi++) { acc2[qi][0] = 0ULL; acc2[qi][1] = 0ULL; }

        #pragma unroll
        for (int ec = 0; ec < 8; ec++) {
            ulonglong2 dv0 = *(const ulonglong2*)&sd[(dth)      * DSTRIDE + ec * 4];
            ulonglong2 dv1 = *(const ulonglong2*)&sd[(dth + 64) * DSTRIDE + ec * 4];
            #pragma unroll
            for (int qi = 0; qi < QPG; qi++) {
                ulonglong2 qv = *(const ulonglong2*)&sq[(qg * QPG + qi) * QSTRIDE + ec * 4];
                ffma2(acc2[qi][0], qv.x, dv0.x);
                ffma2(acc2[qi][0], qv.y, dv0.y);
                ffma2(acc2[qi][1], qv.x, dv1.x);
                ffma2(acc2[qi][1], qv.y, dv1.y);
            }
        }

        int dbase = t * DT;
        #pragma unroll
        for (int j = 0; j < 2; j++) {
            if (dbase + dth + j * 64 < D) {
                #pragma unroll
                for (int qi = 0; qi < QPG; qi++) {
                    float s = hadd2(acc2[qi][j]);
                    if (s > 0.999f) cnt[qi]++;
                    TOPK_INSERT(topk[qi], s);
                }
            }
        }
    }

    // full-warp merge (all 32 lanes hold partials for the same 8 queries)
    #pragma unroll
    for (int qi = 0; qi < QPG; qi++) {
        merge5_warp(topk[qi]);
        #pragma unroll
        for (int off = 16; off >= 1; off >>= 1)
            cnt[qi] += __shfl_xor_sync(0xffffffffu, cnt[qi], off);
    }
    if (lane == 0) {
        #pragma unroll
        for (int qi = 0; qi < QPG; qi++) {
            #pragma unroll
            for (int k = 0; k < KTOP; k++) smerge[warp][qi][k] = topk[qi][k];
            scnt[warp][qi] = cnt[qi];
        }
    }
    __syncthreads();

    // merge the 2 warps of each query group; one thread per query
    if (tid < QT && qbase + tid < Q) {
        int grp = tid >> 3, qi = tid & 7;
        int w0 = 2 * grp, w1 = 2 * grp + 1;
        float A0 = smerge[w0][qi][0], A1 = smerge[w0][qi][1], A2 = smerge[w0][qi][2],
              A3 = smerge[w0][qi][3], A4 = smerge[w0][qi][4];
        float B0 = smerge[w1][qi][0], B1 = smerge[w1][qi][1], B2 = smerge[w1][qi][2],
              B3 = smerge[w1][qi][3], B4 = smerge[w1][qi][4];
        float t5[KTOP];
        #pragma unroll
        for (int k = 0; k < KTOP; k++) {
            bool ta = A0 >= B0;
            t5[k] = ta ? A0 : B0;
            if (ta) { A0 = A1; A1 = A2; A2 = A3; A3 = A4; A4 = -1e30f; }
            else    { B0 = B1; B1 = B2; B2 = B3; B3 = B4; B4 = -1e30f; }
        }
        int c = scnt[w0][qi] + scnt[w1][qi];
        float mean = (t5[0] + t5[1] + t5[2] + t5[3] + t5[4]) * 0.2f;
        g_pool[a * QMAX + qbase + tid] = make_float2(t5[0], mean);
        g_cnt4[a * QMAX + qbase + tid] = c;
    }
}

// ---------------- kernel 4a: per-query MLP partial sums ----------------
__device__ __forceinline__ float mlp_out(const float temp[6],
                                         const float* __restrict__ Wq1,
                                         const float* __restrict__ Wq2)
{
    float out = 0.f;
    #pragma unroll
    for (int h = 0; h < 8; h++) {
        float hh = 0.f;
        #pragma unroll
        for (int j = 0; j < 6; j++) hh += __ldg(&Wq1[h * 6 + j]) * temp[j];
        out += __ldg(&Wq2[h]) * leaky(hh);
    }
    return out;
}

__global__ void __launch_bounds__(256)
combine_partial_kernel(const float* __restrict__ Wq1,
                       const float* __restrict__ Wq2,
                       int Q)
{
    __shared__ float r1[256], r2[256];
    int tid = threadIdx.x;
    float s1 = 0.f, s2 = 0.f;
    for (int q = blockIdx.x * 256 + tid; q < Q; q += CPART * 256) {
        float w = g_qw[q];
        {
            int c = g_cnt4[0 * QMAX + q];
            float2 pi = g_pool[0 * QMAX + q];
            float2 ps = g_pool[2 * QMAX + q];
            float temp[6] = { (c > 0) ? 1.f : 0.f, fminf((float)c, 5.f) * 0.2f,
                              pi.x, pi.y, ps.x, ps.y };
            s1 += mlp_out(temp, Wq1, Wq2) * w;
        }
        {
            int c = g_cnt4[1 * QMAX + q];
            float2 pi = g_pool[1 * QMAX + q];
            float2 ps = g_pool[3 * QMAX + q];
            float temp[6] = { (c > 0) ? 1.f : 0.f, fminf((float)c, 5.f) * 0.2f,
                              pi.x, pi.y, ps.x, ps.y };
            s2 += mlp_out(temp, Wq1, Wq2) * w;
        }
    }
    r1[tid] = s1; r2[tid] = s2; __syncthreads();
    for (int s = 128; s; s >>= 1) {
        if (tid < s) { r1[tid] += r1[tid + s]; r2[tid] += r2[tid + s]; }
        __syncthreads();
    }
    if (tid == 0) g_part[blockIdx.x] = make_float2(r1[0], r2[0]);
}

// ---------------- kernel 4b: finalize ----------------
__global__ void final_kernel(const float* __restrict__ gaf,
                             const float* __restrict__ baf,
                             const float* __restrict__ Wout,
                             float* __restrict__ out, int Q)
{
    if (threadIdx.x == 0) {
        float s1 = 0.f, s2 = 0.f;
        #pragma unroll
        for (int b = 0; b < CPART; b++) { s1 += g_part[b].x; s2 += g_part[b].y; }
        float e1 = s1 / (float)Q;
        float e2 = s2 / (float)Q;
        float good = gaf[0] * Wout[0] + gaf[1] * Wout[1] + gaf[2] * Wout[2]
                   + gaf[3] * Wout[3] + e1 * Wout[4];
        float bad  = baf[0] * Wout[0] + baf[1] * Wout[1] + baf[2] * Wout[2]
                   + baf[3] * Wout[3] + e2 * Wout[4];
        float l = 1.f + bad - good;
        out[0] = (l > 0.f) ? l : 0.f;
        out[1] = good;
        out[2] = bad;
    }
}

// ---------------- launch ----------------
extern "C" void kernel_launch(void* const* d_in, const int* in_sizes, int n_in,
                              void* d_out, int out_size)
{
    const float* d1   = (const float*)d_in[0];
    const float* d2   = (const float*)d_in[1];
    const float* qe   = (const float*)d_in[2];
    const float* qidf = (const float*)d_in[3];
    const float* gaf  = (const float*)d_in[4];
    const float* baf  = (const float*)d_in[5];
    const float* Wc   = (const float*)d_in[6];
    const float* bc   = (const float*)d_in[7];
    const float* Wqw  = (const float*)d_in[8];
    const float* Wq1  = (const float*)d_in[9];
    const float* Wq2  = (const float*)d_in[10];
    const float* Wout = (const float*)d_in[11];

    int D = in_sizes[0] / EMB;
    int Q = in_sizes[2] / EMB;
    if (D > DMAX) D = DMAX;
    if (Q > QMAX) Q = QMAX;

    int totalRows = Q + 2 * D;
    int groups = (totalRows + 7) / 8;
    int convBlocks = groups < 1184 ? groups : 1184;
    conv_kernel<<<convBlocks, 256>>>(qe, d1, d2, qidf, Wc, bc, Wqw, Q, D);

    softmax_kernel<<<1, 256>>>(Q);

    dim3 simGrid((Q + QT - 1) / QT, 4);
    sim_kernel<<<simGrid, THREADS>>>(Q, D);

    combine_partial_kernel<<<CPART, 256>>>(Wq1, Wq2, Q);
    final_kernel<<<1, 32>>>(gaf, baf, Wout, (float*)d_out, Q);
}

// round 7
// speedup vs baseline: 4.4001x; 1.1863x over previous
#include <cuda_runtime.h>
#include <math.h>

#define EMB     30
#define KTOP    5
#define QMAX    2048
#define DMAX    8192
#define QT      32      // queries per sim block (8 per query-group)
#define QPG     8       // queries per group
#define DT      128     // docs per shared tile
#define THREADS 256
#define DSTRIDE 36      // doc tile row stride (floats)
#define QSTRIDE 32      // padded row stride of global operand matrices (floats)
#define NSPLIT  4       // doc-dimension splits for sim grid
#define CPART   8       // combine partial blocks

// ---------------- device scratch (static; zero-initialized) ----------------
__device__ float g_qN  [QMAX * QSTRIDE];
__device__ float g_qcN [QMAX * QSTRIDE];
__device__ float g_d1N [DMAX * QSTRIDE];
__device__ float g_d2N [DMAX * QSTRIDE];
__device__ float g_d1cN[DMAX * QSTRIDE];
__device__ float g_d2cN[DMAX * QSTRIDE];
__device__ float g_logits[QMAX];
__device__ float g_qw    [QMAX];
__device__ float g_top5p[4 * NSPLIT * QMAX * KTOP];   // partial top-5 per (array,split,q)
__device__ int   g_cntp [4 * NSPLIT * QMAX];          // partial counts
__device__ float2 g_part [CPART];

__device__ __forceinline__ float leaky(float x) { return x > 0.f ? x : 0.1f * x; }

__device__ __forceinline__ void ffma2(unsigned long long& acc,
                                      unsigned long long a,
                                      unsigned long long b)
{
    asm("fma.rn.f32x2 %0, %1, %2, %0;" : "+l"(acc) : "l"(a), "l"(b));
}
__device__ __forceinline__ float hadd2(unsigned long long v)
{
    float lo = __uint_as_float((unsigned)(v & 0xffffffffULL));
    float hi = __uint_as_float((unsigned)(v >> 32));
    return lo + hi;
}

// ---------------- kernel 1: conv + residual + norms ----------------
__global__ void __launch_bounds__(256)
conv_kernel(const float* __restrict__ qe,
            const float* __restrict__ d1,
            const float* __restrict__ d2,
            const float* __restrict__ qidf,
            const float* __restrict__ Wc,   // [30,30,3] = 2700
            const float* __restrict__ bc,   // [30]
            const float* __restrict__ Wqw,  // [31]
            int Q, int D)
{
    __shared__ float sWc[2700];
    __shared__ float sbc[30];
    __shared__ float sWqw[31];
    int tid = threadIdx.x;
    for (int i = tid; i < 2700; i += 256) sWc[i] = __ldg(&Wc[i]);
    if (tid < 30) sbc[tid] = __ldg(&bc[tid]);
    if (tid < 31) sWqw[tid] = __ldg(&Wqw[tid]);
    __syncthreads();

    int warp = tid >> 5;
    int lane = tid & 31;
    int total  = Q + 2 * D;
    int groups = (total + 7) >> 3;

    for (int g = blockIdx.x; g < groups; g += gridDim.x) {
        int gw = g * 8 + warp;
        if (gw >= total) continue;

        const float* x; float* yN; float* xN; int L, l, which;
        if (gw < Q)          { x = qe; yN = g_qcN;  xN = g_qN;  L = Q; l = gw;         which = 0; }
        else if (gw < Q + D) { x = d1; yN = g_d1cN; xN = g_d1N; L = D; l = gw - Q;     which = 1; }
        else                 { x = d2; yN = g_d2cN; xN = g_d2N; L = D; l = gw - Q - D; which = 2; }

        int o = lane;
        float yv = 0.f, xval = 0.f;
        if (o < EMB) {
            float acc = sbc[o];
            #pragma unroll
            for (int t = 0; t < 3; t++) {
                int ll = l + t - 1;
                if (ll >= 0 && ll < L) {
                    const float* xr = x + (size_t)ll * EMB;
                    #pragma unroll
                    for (int i = 0; i < EMB; i++)
                        acc += __ldg(&xr[i]) * sWc[o * 90 + i * 3 + t];
                }
            }
            xval = __ldg(&x[(size_t)l * EMB + o]);
            yv = leaky(acc) + xval;
        }

        float s_conv = yv * yv;
        float s_orig = xval * xval;
        float lg = (which == 0 && o < EMB) ? yv * sWqw[o] : 0.f;
        #pragma unroll
        for (int off = 16; off; off >>= 1) {
            s_conv += __shfl_xor_sync(0xffffffffu, s_conv, off);
            s_orig += __shfl_xor_sync(0xffffffffu, s_orig, off);
            lg     += __shfl_xor_sync(0xffffffffu, lg,     off);
        }
        float ic = rsqrtf(s_conv);
        float io = rsqrtf(s_orig);
        yN[(size_t)l * QSTRIDE + o] = yv * ic;
        xN[(size_t)l * QSTRIDE + o] = xval * io;
        if (which == 0 && lane == 0)
            g_logits[l] = lg + __ldg(&qidf[l]) * sWqw[EMB];
    }
}

// ---------------- kernel 2: softmax over Q logits ----------------
__global__ void __launch_bounds__(256)
softmax_kernel(int Q)
{
    __shared__ float red[256];
    int tid = threadIdx.x;
    float m = -1e30f;
    for (int i = tid; i < Q; i += 256) m = fmaxf(m, g_logits[i]);
    red[tid] = m; __syncthreads();
    for (int s = 128; s; s >>= 1) {
        if (tid < s) red[tid] = fmaxf(red[tid], red[tid + s]);
        __syncthreads();
    }
    float mx = red[0];
    __syncthreads();
    float sum = 0.f;
    for (int i = tid; i < Q; i += 256) sum += expf(g_logits[i] - mx);
    red[tid] = sum; __syncthreads();
    for (int s = 128; s; s >>= 1) {
        if (tid < s) red[tid] += red[tid + s];
        __syncthreads();
    }
    float inv = 1.f / red[0];
    for (int i = tid; i < Q; i += 256)
        g_qw[i] = expf(g_logits[i] - mx) * inv;
}

// ---------------- top-5 helpers ----------------
#define TOPK_INSERT(t, v) do {                                        \
    float _v = (v);                                                   \
    if (_v > t[4]) {                                                  \
        t[4] = _v; float _tmp;                                        \
        if (t[4] > t[3]) { _tmp = t[3]; t[3] = t[4]; t[4] = _tmp; }   \
        if (t[3] > t[2]) { _tmp = t[2]; t[2] = t[3]; t[3] = _tmp; }   \
        if (t[2] > t[1]) { _tmp = t[1]; t[1] = t[2]; t[2] = _tmp; }   \
        if (t[1] > t[0]) { _tmp = t[0]; t[0] = t[1]; t[1] = _tmp; }   \
    } } while (0)

__device__ __forceinline__ void merge5_warp(float t[KTOP])
{
    #pragma unroll
    for (int off = 16; off >= 1; off >>= 1) {
        float b0 = __shfl_xor_sync(0xffffffffu, t[0], off);
        float b1 = __shfl_xor_sync(0xffffffffu, t[1], off);
        float b2 = __shfl_xor_sync(0xffffffffu, t[2], off);
        float b3 = __shfl_xor_sync(0xffffffffu, t[3], off);
        float b4 = __shfl_xor_sync(0xffffffffu, t[4], off);
        float a0 = t[0], a1 = t[1], a2 = t[2], a3 = t[3], a4 = t[4];
        #pragma unroll
        for (int k = 0; k < KTOP; k++) {
            bool ta = a0 >= b0;
            t[k] = ta ? a0 : b0;
            if (ta) { a0 = a1; a1 = a2; a2 = a3; a3 = a4; a4 = -1e30f; }
            else    { b0 = b1; b1 = b2; b2 = b3; b3 = b4; b4 = -1e30f; }
        }
    }
}

// ---------------- kernel 3: sims, doc-split grid, double-buffered, 2 blocks/SM --------
__global__ void __launch_bounds__(THREADS, 2)
sim_kernel(int Q, int D)
{
    __shared__ float sq[QT * QSTRIDE];          // 4 KB
    __shared__ float sd[2][DT * DSTRIDE];       // 36 KB
    __shared__ float smerge[8][QPG][KTOP];
    __shared__ int   scnt[8][QPG];

    int a     = blockIdx.y & 3;
    int split = blockIdx.y >> 2;
    int qbase = blockIdx.x * QT;
    const float* Aq = (a < 2) ? g_qN : g_qcN;
    const float* Bd = (a == 0) ? g_d1N : (a == 1) ? g_d2N
                    : (a == 2) ? g_d1cN : g_d2cN;

    int chunk  = (D + NSPLIT - 1) / NSPLIT;
    int dstart = split * chunk;
    int dend   = min(D, dstart + chunk);

    int tid  = threadIdx.x;
    int warp = tid >> 5;
    int lane = tid & 31;
    int qg   = tid >> 6;       // 0..3, uniform within warp
    int dth  = tid & 63;       // 0..63

    // stage query tile: 32 rows x 8 float4 = 256 float4
    {
        int r = tid >> 3, ec = tid & 7;
        int qq = qbase + r;
        float4 v = (qq < QMAX) ? *(const float4*)&Aq[(size_t)qq * QSTRIDE + ec * 4]
                               : make_float4(0.f, 0.f, 0.f, 0.f);
        *(float4*)&sq[r * QSTRIDE + ec * 4] = v;
    }

    float topk[QPG][KTOP];
    int cnt[QPG];
    #pragma unroll
    for (int qi = 0; qi < QPG; qi++) {
        cnt[qi] = 0;
        #pragma unroll
        for (int k = 0; k < KTOP; k++) topk[qi][k] = -1e30f;
    }

    int ntiles = (dend - dstart + DT - 1) / DT;

    // prefetch tile 0 (4 float4 per thread), store to buffer 0
    float4 pf[4];
    #pragma unroll
    for (int k = 0; k < 4; k++) {
        int i = tid + k * THREADS;
        int r = i >> 3, ec = i & 7;
        pf[k] = *(const float4*)&Bd[(size_t)(dstart + r) * QSTRIDE + ec * 4];
    }
    #pragma unroll
    for (int k = 0; k < 4; k++) {
        int i = tid + k * THREADS;
        int r = i >> 3, ec = i & 7;
        *(float4*)&sd[0][r * DSTRIDE + ec * 4] = pf[k];
    }
    __syncthreads();

    for (int t = 0; t < ntiles; t++) {
        int cur = t & 1;

        // issue next tile's global loads (latency hidden under compute)
        if (t + 1 < ntiles) {
            int dnext = dstart + (t + 1) * DT;
            #pragma unroll
            for (int k = 0; k < 4; k++) {
                int i = tid + k * THREADS;
                int r = i >> 3, ec = i & 7;
                pf[k] = *(const float4*)&Bd[(size_t)(dnext + r) * QSTRIDE + ec * 4];
            }
        }

        unsigned long long acc2[QPG][2];
        #pragma unroll
        for (int qi = 0; qi < QPG; qi++) { acc2[qi][0] = 0ULL; acc2[qi][1] = 0ULL; }

        #pragma unroll
        for (int ec = 0; ec < 8; ec++) {
            ulonglong2 dv0 = *(const ulonglong2*)&sd[cur][(dth)      * DSTRIDE + ec * 4];
            ulonglong2 dv1 = *(const ulonglong2*)&sd[cur][(dth + 64) * DSTRIDE + ec * 4];
            #pragma unroll
            for (int qi = 0; qi < QPG; qi++) {
                ulonglong2 qv = *(const ulonglong2*)&sq[(qg * QPG + qi) * QSTRIDE + ec * 4];
                ffma2(acc2[qi][0], qv.x, dv0.x);
                ffma2(acc2[qi][0], qv.y, dv0.y);
                ffma2(acc2[qi][1], qv.x, dv1.x);
                ffma2(acc2[qi][1], qv.y, dv1.y);
            }
        }

        int dbase = dstart + t * DT;
        #pragma unroll
        for (int j = 0; j < 2; j++) {
            if (dbase + dth + j * 64 < dend) {
                #pragma unroll
                for (int qi = 0; qi < QPG; qi++) {
                    float s = hadd2(acc2[qi][j]);
                    if (s > 0.999f) cnt[qi]++;
                    TOPK_INSERT(topk[qi], s);
                }
            }
        }

        // store prefetched tile into the other buffer
        if (t + 1 < ntiles) {
            #pragma unroll
            for (int k = 0; k < 4; k++) {
                int i = tid + k * THREADS;
                int r = i >> 3, ec = i & 7;
                *(float4*)&sd[1 - cur][r * DSTRIDE + ec * 4] = pf[k];
            }
        }
        __syncthreads();
    }

    // full-warp merge
    #pragma unroll
    for (int qi = 0; qi < QPG; qi++) {
        merge5_warp(topk[qi]);
        #pragma unroll
        for (int off = 16; off >= 1; off >>= 1)
            cnt[qi] += __shfl_xor_sync(0xffffffffu, cnt[qi], off);
    }
    if (lane == 0) {
        #pragma unroll
        for (int qi = 0; qi < QPG; qi++) {
            #pragma unroll
            for (int k = 0; k < KTOP; k++) smerge[warp][qi][k] = topk[qi][k];
            scnt[warp][qi] = cnt[qi];
        }
    }
    __syncthreads();

    // merge the 2 warps per query group; write partials to global
    if (tid < QT && qbase + tid < Q) {
        int grp = tid >> 3, qi = tid & 7;
        int w0 = 2 * grp, w1 = 2 * grp + 1;
        float A0 = smerge[w0][qi][0], A1 = smerge[w0][qi][1], A2 = smerge[w0][qi][2],
              A3 = smerge[w0][qi][3], A4 = smerge[w0][qi][4];
        float B0 = smerge[w1][qi][0], B1 = smerge[w1][qi][1], B2 = smerge[w1][qi][2],
              B3 = smerge[w1][qi][3], B4 = smerge[w1][qi][4];
        float t5[KTOP];
        #pragma unroll
        for (int k = 0; k < KTOP; k++) {
            bool ta = A0 >= B0;
            t5[k] = ta ? A0 : B0;
            if (ta) { A0 = A1; A1 = A2; A2 = A3; A3 = A4; A4 = -1e30f; }
            else    { B0 = B1; B1 = B2; B2 = B3; B3 = B4; B4 = -1e30f; }
        }
        int q = qbase + tid;
        size_t base = ((size_t)(a * NSPLIT + split) * QMAX + q) * KTOP;
        #pragma unroll
        for (int k = 0; k < KTOP; k++) g_top5p[base + k] = t5[k];
        g_cntp[(a * NSPLIT + split) * QMAX + q] = scnt[w0][qi] + scnt[w1][qi];
    }
}

// ---------------- kernel 4a: merge splits + per-query MLP partial sums ----------------
__device__ __forceinline__ float mlp_out(const float temp[6],
                                         const float* __restrict__ Wq1,
                                         const float* __restrict__ Wq2)
{
    float out = 0.f;
    #pragma unroll
    for (int h = 0; h < 8; h++) {
        float hh = 0.f;
        #pragma unroll
        for (int j = 0; j < 6; j++) hh += __ldg(&Wq1[h * 6 + j]) * temp[j];
        out += __ldg(&Wq2[h]) * leaky(hh);
    }
    return out;
}

__device__ __forceinline__ void merge_splits(int a, int q, float t[KTOP], int& c)
{
    #pragma unroll
    for (int k = 0; k < KTOP; k++) t[k] = -1e30f;
    c = 0;
    #pragma unroll
    for (int s = 0; s < NSPLIT; s++) {
        size_t base = ((size_t)(a * NSPLIT + s) * QMAX + q) * KTOP;
        c += g_cntp[(a * NSPLIT + s) * QMAX + q];
        #pragma unroll
        for (int k = 0; k < KTOP; k++) TOPK_INSERT(t, g_top5p[base + k]);
    }
}

__global__ void __launch_bounds__(256)
combine_partial_kernel(const float* __restrict__ Wq1,
                       const float* __restrict__ Wq2,
                       int Q)
{
    __shared__ float r1[256], r2[256];
    int tid = threadIdx.x;
    float s1 = 0.f, s2 = 0.f;
    for (int q = blockIdx.x * 256 + tid; q < Q; q += CPART * 256) {
        float w = g_qw[q];
        float ti[KTOP], ts[KTOP];
        int ci, cs;
        // doc1: arrays 0 (interaction) and 2 (semantic)
        merge_splits(0, q, ti, ci);
        merge_splits(2, q, ts, cs);
        {
            float temp[6] = { (ci > 0) ? 1.f : 0.f, fminf((float)ci, 5.f) * 0.2f,
                              ti[0], (ti[0]+ti[1]+ti[2]+ti[3]+ti[4]) * 0.2f,
                              ts[0], (ts[0]+ts[1]+ts[2]+ts[3]+ts[4]) * 0.2f };
            s1 += mlp_out(temp, Wq1, Wq2) * w;
        }
        // doc2: arrays 1 and 3
        merge_splits(1, q, ti, ci);
        merge_splits(3, q, ts, cs);
        {
            float temp[6] = { (ci > 0) ? 1.f : 0.f, fminf((float)ci, 5.f) * 0.2f,
                              ti[0], (ti[0]+ti[1]+ti[2]+ti[3]+ti[4]) * 0.2f,
                              ts[0], (ts[0]+ts[1]+ts[2]+ts[3]+ts[4]) * 0.2f };
            s2 += mlp_out(temp, Wq1, Wq2) * w;
        }
    }
    r1[tid] = s1; r2[tid] = s2; __syncthreads();
    for (int s = 128; s; s >>= 1) {
        if (tid < s) { r1[tid] += r1[tid + s]; r2[tid] += r2[tid + s]; }
        __syncthreads();
    }
    if (tid == 0) g_part[blockIdx.x] = make_float2(r1[0], r2[0]);
}

// ---------------- kernel 4b: finalize ----------------
__global__ void final_kernel(const float* __restrict__ gaf,
                             const float* __restrict__ baf,
                             const float* __restrict__ Wout,
                             float* __restrict__ out, int Q)
{
    if (threadIdx.x == 0) {
        float s1 = 0.f, s2 = 0.f;
        #pragma unroll
        for (int b = 0; b < CPART; b++) { s1 += g_part[b].x; s2 += g_part[b].y; }
        float e1 = s1 / (float)Q;
        float e2 = s2 / (float)Q;
        float good = gaf[0] * Wout[0] + gaf[1] * Wout[1] + gaf[2] * Wout[2]
                   + gaf[3] * Wout[3] + e1 * Wout[4];
        float bad  = baf[0] * Wout[0] + baf[1] * Wout[1] + baf[2] * Wout[2]
                   + baf[3] * Wout[3] + e2 * Wout[4];
        float l = 1.f + bad - good;
        out[0] = (l > 0.f) ? l : 0.f;
        out[1] = good;
        out[2] = bad;
    }
}

// ---------------- launch ----------------
extern "C" void kernel_launch(void* const* d_in, const int* in_sizes, int n_in,
                              void* d_out, int out_size)
{
    const float* d1   = (const float*)d_in[0];
    const float* d2   = (const float*)d_in[1];
    const float* qe   = (const float*)d_in[2];
    const float* qidf = (const float*)d_in[3];
    const float* gaf  = (const float*)d_in[4];
    const float* baf  = (const float*)d_in[5];
    const float* Wc   = (const float*)d_in[6];
    const float* bc   = (const float*)d_in[7];
    const float* Wqw  = (const float*)d_in[8];
    const float* Wq1  = (const float*)d_in[9];
    const float* Wq2  = (const float*)d_in[10];
    const float* Wout = (const float*)d_in[11];

    int D = in_sizes[0] / EMB;
    int Q = in_sizes[2] / EMB;
    if (D > DMAX) D = DMAX;
    if (Q > QMAX) Q = QMAX;

    int totalRows = Q + 2 * D;
    int groups = (totalRows + 7) / 8;
    int convBlocks = groups < 1184 ? groups : 1184;
    conv_kernel<<<convBlocks, 256>>>(qe, d1, d2, qidf, Wc, bc, Wqw, Q, D);

    softmax_kernel<<<1, 256>>>(Q);

    dim3 simGrid((Q + QT - 1) / QT, 4 * NSPLIT);
    sim_kernel<<<simGrid, THREADS>>>(Q, D);

    combine_partial_kernel<<<CPART, 256>>>(Wq1, Wq2, Q);
    final_kernel<<<1, 32>>>(gaf, baf, Wout, (float*)d_out, Q);
}